// round 1
// baseline (speedup 1.0000x reference)
#include <cuda_runtime.h>
#include <math.h>

#define BB 2
#define SQ 1024
#define DD 768
#define NH 12
#define DK 64
#define FF 3072
#define NL 12
#define NV 50257
#define NT (BB*SQ)   // 2048 tokens

// ---------------- scratch (allocation-free: __device__ globals) ----------------
__device__ float g_x  [NT*DD];
__device__ float g_q  [NT*DD];
__device__ float g_k  [NT*DD];
__device__ float g_v  [NT*DD];
__device__ float g_ctx[NT*DD];
__device__ float g_tmp[NT*DD];
__device__ float g_h  [NT*FF];
__device__ float g_sc [(size_t)BB*NH*SQ*SQ];   // attention scores, ~100 MB

// ---------------- embedding ----------------
__global__ void k_embed(const int* __restrict__ ids, const float* __restrict__ emb,
                        const float* __restrict__ pe, float* __restrict__ x)
{
    int i = blockIdx.x * 256 + threadIdx.x;
    if (i >= NT * DD) return;
    int t = i / DD;
    int d = i - t * DD;
    int s = t % SQ;
    x[i] = emb[(size_t)ids[t] * DD + d] + pe[(size_t)s * DD + d];
}

// ---------------- generic SGEMM: C = act(A[M,K] @ B[K,N] + bias) ----------------
// 64x64 tile, BK=16, 256 threads, 4x4 per-thread microtile.
// M multiple of 64, K multiple of 16 (true for all uses). N guarded.
__global__ void k_sgemm(const float* __restrict__ A, const float* __restrict__ Bm,
                        const float* __restrict__ bias, float* __restrict__ C,
                        int M, int N, int K, int act)
{
    __shared__ float As[16][64];
    __shared__ float Bs[16][64];

    int tid = threadIdx.x;
    int ty = tid >> 4, tx = tid & 15;
    int m0 = blockIdx.y * 64, n0 = blockIdx.x * 64;

    float acc[4][4] = {};

    for (int k0 = 0; k0 < K; k0 += 16) {
        // A tile (float4, always in-bounds)
        {
            int row = tid >> 2;
            int c4  = (tid & 3) * 4;
            float4 av = *(const float4*)(A + (size_t)(m0 + row) * K + k0 + c4);
            As[c4+0][row] = av.x; As[c4+1][row] = av.y;
            As[c4+2][row] = av.z; As[c4+3][row] = av.w;
        }
        // B tile (scalar, N-guarded; N may be odd -> no vector loads)
        {
            int kr = tid >> 4;
            int nc = (tid & 15) * 4;
            const float* bp = Bm + (size_t)(k0 + kr) * N + n0 + nc;
            #pragma unroll
            for (int j = 0; j < 4; j++) {
                int n = n0 + nc + j;
                Bs[kr][nc + j] = (n < N) ? bp[j] : 0.f;
            }
        }
        __syncthreads();
        #pragma unroll
        for (int kk = 0; kk < 16; kk++) {
            float a[4], b[4];
            #pragma unroll
            for (int i = 0; i < 4; i++) a[i] = As[kk][ty*4 + i];
            #pragma unroll
            for (int j = 0; j < 4; j++) b[j] = Bs[kk][tx*4 + j];
            #pragma unroll
            for (int i = 0; i < 4; i++)
                #pragma unroll
                for (int j = 0; j < 4; j++)
                    acc[i][j] += a[i] * b[j];
        }
        __syncthreads();
    }

    #pragma unroll
    for (int i = 0; i < 4; i++) {
        int m = m0 + ty*4 + i;
        #pragma unroll
        for (int j = 0; j < 4; j++) {
            int n = n0 + tx*4 + j;
            if (n < N) {
                float v = acc[i][j];
                if (bias) v += bias[n];
                if (act == 1) v = 0.5f * v * (1.f + erff(v * 0.70710678118654752f));
                C[(size_t)m * N + n] = v;
            }
        }
    }
}

// ---------------- attention scores: S[bh,i,j] = (Q_i . K_j) / 8 ----------------
__global__ void k_scores(const float* __restrict__ Q, const float* __restrict__ Kv,
                         float* __restrict__ Sc)
{
    int bh = blockIdx.z;
    int b = bh / NH, h = bh - b * NH;
    const float* qb = Q  + (size_t)b * SQ * DD + h * DK;
    const float* kb = Kv + (size_t)b * SQ * DD + h * DK;
    float* sb = Sc + (size_t)bh * SQ * SQ;

    int i0 = blockIdx.y * 64, j0 = blockIdx.x * 64;
    __shared__ float Qs[16][64];
    __shared__ float Ks[16][64];

    int tid = threadIdx.x;
    int ty = tid >> 4, tx = tid & 15;
    float acc[4][4] = {};

    for (int k0 = 0; k0 < DK; k0 += 16) {
        int row = tid >> 2;
        int c4  = (tid & 3) * 4;
        float4 qv = *(const float4*)(qb + (size_t)(i0 + row) * DD + k0 + c4);
        Qs[c4+0][row] = qv.x; Qs[c4+1][row] = qv.y;
        Qs[c4+2][row] = qv.z; Qs[c4+3][row] = qv.w;
        float4 kv = *(const float4*)(kb + (size_t)(j0 + row) * DD + k0 + c4);
        Ks[c4+0][row] = kv.x; Ks[c4+1][row] = kv.y;
        Ks[c4+2][row] = kv.z; Ks[c4+3][row] = kv.w;
        __syncthreads();
        #pragma unroll
        for (int kk = 0; kk < 16; kk++) {
            float a[4], bb_[4];
            #pragma unroll
            for (int i = 0; i < 4; i++) a[i]  = Qs[kk][ty*4 + i];
            #pragma unroll
            for (int j = 0; j < 4; j++) bb_[j] = Ks[kk][tx*4 + j];
            #pragma unroll
            for (int i = 0; i < 4; i++)
                #pragma unroll
                for (int j = 0; j < 4; j++)
                    acc[i][j] += a[i] * bb_[j];
        }
        __syncthreads();
    }

    const float scale = 0.125f;  // 1/sqrt(64)
    #pragma unroll
    for (int i = 0; i < 4; i++)
        #pragma unroll
        for (int j = 0; j < 4; j++)
            sb[(size_t)(i0 + ty*4 + i) * SQ + (j0 + tx*4 + j)] = acc[i][j] * scale;
}

// ---------------- masked softmax over last dim (row length SQ) ----------------
__global__ void k_softmax(float* __restrict__ Sc, const int* __restrict__ mask)
{
    int r  = blockIdx.x;                  // 0 .. B*H*SQ-1
    int bh = r / SQ;
    int b  = bh / NH;
    float* row = Sc + (size_t)r * SQ;
    const int* mrow = mask + (size_t)b * SQ;

    int tid = threadIdx.x;
    __shared__ float rbuf[8];

    float v[4];
    float mx = -1e30f;
    #pragma unroll
    for (int j = 0; j < 4; j++) {
        int c = j * 256 + tid;
        float x = row[c];
        if (mrow[c] == 0) x = -1e9f;
        v[j] = x;
        mx = fmaxf(mx, x);
    }
    // block max
    #pragma unroll
    for (int o = 16; o; o >>= 1) mx = fmaxf(mx, __shfl_xor_sync(0xffffffffu, mx, o));
    __syncthreads();
    if ((tid & 31) == 0) rbuf[tid >> 5] = mx;
    __syncthreads();
    mx = rbuf[0];
    #pragma unroll
    for (int w = 1; w < 8; w++) mx = fmaxf(mx, rbuf[w]);

    float s = 0.f;
    #pragma unroll
    for (int j = 0; j < 4; j++) { v[j] = expf(v[j] - mx); s += v[j]; }
    #pragma unroll
    for (int o = 16; o; o >>= 1) s += __shfl_xor_sync(0xffffffffu, s, o);
    __syncthreads();
    if ((tid & 31) == 0) rbuf[tid >> 5] = s;
    __syncthreads();
    s = rbuf[0];
    #pragma unroll
    for (int w = 1; w < 8; w++) s += rbuf[w];
    float inv = 1.f / s;

    #pragma unroll
    for (int j = 0; j < 4; j++) row[j * 256 + tid] = v[j] * inv;
}

// ---------------- ctx = P @ V (per batch-head) ----------------
__global__ void k_ctx(const float* __restrict__ P, const float* __restrict__ Vv,
                      float* __restrict__ C)
{
    int bh = blockIdx.z;
    int b = bh / NH, h = bh - b * NH;
    const float* pb = P  + (size_t)bh * SQ * SQ;
    const float* vb = Vv + (size_t)b * SQ * DD + h * DK;
    float* cb = C + (size_t)b * SQ * DD + h * DK;

    int i0 = blockIdx.y * 64;
    __shared__ float As[16][64];
    __shared__ float Bs[16][64];

    int tid = threadIdx.x;
    int ty = tid >> 4, tx = tid & 15;
    float acc[4][4] = {};

    for (int k0 = 0; k0 < SQ; k0 += 16) {
        {
            int row = tid >> 2;
            int c4  = (tid & 3) * 4;
            float4 av = *(const float4*)(pb + (size_t)(i0 + row) * SQ + k0 + c4);
            As[c4+0][row] = av.x; As[c4+1][row] = av.y;
            As[c4+2][row] = av.z; As[c4+3][row] = av.w;
        }
        {
            int kr = tid >> 4;
            int nc = (tid & 15) * 4;
            float4 bv = *(const float4*)(vb + (size_t)(k0 + kr) * DD + nc);
            Bs[kr][nc+0] = bv.x; Bs[kr][nc+1] = bv.y;
            Bs[kr][nc+2] = bv.z; Bs[kr][nc+3] = bv.w;
        }
        __syncthreads();
        #pragma unroll
        for (int kk = 0; kk < 16; kk++) {
            float a[4], bb_[4];
            #pragma unroll
            for (int i = 0; i < 4; i++) a[i]  = As[kk][ty*4 + i];
            #pragma unroll
            for (int j = 0; j < 4; j++) bb_[j] = Bs[kk][tx*4 + j];
            #pragma unroll
            for (int i = 0; i < 4; i++)
                #pragma unroll
                for (int j = 0; j < 4; j++)
                    acc[i][j] += a[i] * bb_[j];
        }
        __syncthreads();
    }

    #pragma unroll
    for (int i = 0; i < 4; i++)
        #pragma unroll
        for (int j = 0; j < 4; j++)
            cb[(size_t)(i0 + ty*4 + i) * DD + tx*4 + j] = acc[i][j];
}

// ---------------- out = LayerNorm(x (+ res)) * g + b ----------------
// one block per token row, 256 threads x 3 elems = 768
__global__ void k_addln(const float* __restrict__ X, const float* __restrict__ R,
                        const float* __restrict__ g, const float* __restrict__ bb,
                        float* __restrict__ O)
{
    int r = blockIdx.x;
    const float* xr = X + (size_t)r * DD;
    const float* rr = R ? (R + (size_t)r * DD) : nullptr;
    float* orow = O + (size_t)r * DD;

    int tid = threadIdx.x;
    __shared__ float rbuf[8];

    float v[3];
    float s = 0.f;
    #pragma unroll
    for (int j = 0; j < 3; j++) {
        int c = tid * 3 + j;
        float x = xr[c];
        if (rr) x += rr[c];
        v[j] = x;
        s += x;
    }
    #pragma unroll
    for (int o = 16; o; o >>= 1) s += __shfl_xor_sync(0xffffffffu, s, o);
    __syncthreads();
    if ((tid & 31) == 0) rbuf[tid >> 5] = s;
    __syncthreads();
    s = rbuf[0];
    #pragma unroll
    for (int w = 1; w < 8; w++) s += rbuf[w];
    float mean = s * (1.f / DD);

    float s2 = 0.f;
    #pragma unroll
    for (int j = 0; j < 3; j++) { float d = v[j] - mean; s2 += d * d; }
    #pragma unroll
    for (int o = 16; o; o >>= 1) s2 += __shfl_xor_sync(0xffffffffu, s2, o);
    __syncthreads();
    if ((tid & 31) == 0) rbuf[tid >> 5] = s2;
    __syncthreads();
    s2 = rbuf[0];
    #pragma unroll
    for (int w = 1; w < 8; w++) s2 += rbuf[w];
    float rstd = rsqrtf(s2 * (1.f / DD) + 1e-5f);

    #pragma unroll
    for (int j = 0; j < 3; j++) {
        int c = tid * 3 + j;
        orow[c] = (v[j] - mean) * rstd * g[c] + bb[c];
    }
}

// ---------------- driver ----------------
extern "C" void kernel_launch(void* const* d_in, const int* in_sizes, int n_in,
                              void* d_out, int out_size)
{
    const int*   ids  = (const int*)  d_in[0];
    const int*   mask = (const int*)  d_in[1];
    const float* emb  = (const float*)d_in[2];
    const float* pe   = (const float*)d_in[3];
    const float* Wq   = (const float*)d_in[4];
    const float* Wk   = (const float*)d_in[5];
    const float* Wv   = (const float*)d_in[6];
    const float* Wo   = (const float*)d_in[7];
    const float* ln1g = (const float*)d_in[8];
    const float* ln1b = (const float*)d_in[9];
    const float* ln2g = (const float*)d_in[10];
    const float* ln2b = (const float*)d_in[11];
    const float* W1   = (const float*)d_in[12];
    const float* b1   = (const float*)d_in[13];
    const float* W2   = (const float*)d_in[14];
    const float* b2   = (const float*)d_in[15];
    const float* lnfg = (const float*)d_in[16];
    const float* lnfb = (const float*)d_in[17];
    const float* Wout = (const float*)d_in[18];
    const float* bout = (const float*)d_in[19];
    float* out = (float*)d_out;

    float *x, *q, *k, *v, *ctx, *tmp, *h, *sc;
    cudaGetSymbolAddress((void**)&x,   g_x);
    cudaGetSymbolAddress((void**)&q,   g_q);
    cudaGetSymbolAddress((void**)&k,   g_k);
    cudaGetSymbolAddress((void**)&v,   g_v);
    cudaGetSymbolAddress((void**)&ctx, g_ctx);
    cudaGetSymbolAddress((void**)&tmp, g_tmp);
    cudaGetSymbolAddress((void**)&h,   g_h);
    cudaGetSymbolAddress((void**)&sc,  g_sc);

    // embedding
    k_embed<<<(NT * DD + 255) / 256, 256>>>(ids, emb, pe, x);

    dim3 gD((DD + 63) / 64, NT / 64);         // N=768
    dim3 gF((FF + 63) / 64, NT / 64);         // N=3072
    dim3 gV((NV + 63) / 64, NT / 64);         // N=50257
    dim3 gS(SQ / 64, SQ / 64, BB * NH);       // scores tiles
    dim3 gC(1, SQ / 64, BB * NH);             // ctx tiles

    for (int l = 0; l < NL; l++) {
        const float* wq = Wq + (size_t)l * DD * DD;
        const float* wk = Wk + (size_t)l * DD * DD;
        const float* wv = Wv + (size_t)l * DD * DD;
        const float* wo = Wo + (size_t)l * DD * DD;

        k_sgemm<<<gD, 256>>>(x, wq, nullptr, q, NT, DD, DD, 0);
        k_sgemm<<<gD, 256>>>(x, wk, nullptr, k, NT, DD, DD, 0);
        k_sgemm<<<gD, 256>>>(x, wv, nullptr, v, NT, DD, DD, 0);

        k_scores <<<gS, 256>>>(q, k, sc);
        k_softmax<<<BB * NH * SQ, 256>>>(sc, mask);
        k_ctx    <<<gC, 256>>>(sc, v, ctx);

        k_sgemm<<<gD, 256>>>(ctx, wo, nullptr, tmp, NT, DD, DD, 0);
        k_addln<<<NT, 256>>>(x, tmp, ln1g + (size_t)l * DD, ln1b + (size_t)l * DD, x);

        k_sgemm<<<gF, 256>>>(x, W1 + (size_t)l * DD * FF, b1 + (size_t)l * FF, h, NT, FF, DD, 1);
        k_sgemm<<<gD, 256>>>(h, W2 + (size_t)l * FF * DD, b2 + (size_t)l * DD, tmp, NT, DD, FF, 0);
        k_addln<<<NT, 256>>>(x, tmp, ln2g + (size_t)l * DD, ln2b + (size_t)l * DD, x);
    }

    // final layernorm
    k_addln<<<NT, 256>>>(x, nullptr, lnfg, lnfb, x);

    // logits = x @ Wout + bout
    k_sgemm<<<gV, 256>>>(x, Wout, bout, out, NT, NV, DD, 0);
}

// round 2
// speedup vs baseline: 1.1496x; 1.1496x over previous
#include <cuda_runtime.h>
#include <math.h>

#define BB 2
#define SQ 1024
#define DD 768
#define NH 12
#define DK 64
#define FF 3072
#define NL 12
#define NV 50257
#define NT (BB*SQ)   // 2048 tokens

// ---------------- scratch (allocation-free: __device__ globals) ----------------
__device__ float g_x  [NT*DD];
__device__ float g_q  [NT*DD];
__device__ float g_k  [NT*DD];
__device__ float g_v  [NT*DD];
__device__ float g_ctx[NT*DD];
__device__ float g_tmp[NT*DD];
__device__ float g_h  [NT*FF];
__device__ float g_sc [(size_t)BB*NH*SQ*SQ];   // attention scores, ~100 MB

// ---------------- embedding ----------------
__global__ void k_embed(const int* __restrict__ ids, const float* __restrict__ emb,
                        const float* __restrict__ pe, float* __restrict__ x)
{
    int i = blockIdx.x * 256 + threadIdx.x;
    if (i >= NT * DD) return;
    int t = i / DD;
    int d = i - t * DD;
    int s = t % SQ;
    x[i] = emb[(size_t)ids[t] * DD + d] + pe[(size_t)s * DD + d];
}

__device__ __forceinline__ float gelu_f(float v) {
    return 0.5f * v * (1.f + erff(v * 0.70710678118654752f));
}

// ---------------- big SGEMM: C = act(A[M,K] @ B[K,N] + bias) ----------------
// 128x128 block tile, BK=16, 256 threads, 8x8 per-thread microtile,
// register prefetch of next k-tile. M % 128 == 0, K % 16 == 0 assumed.
__global__ void __launch_bounds__(256, 2)
k_gemm(const float* __restrict__ A, const float* __restrict__ B,
       const float* __restrict__ bias, float* __restrict__ C,
       int M, int N, int K, int act)
{
    __shared__ float As[16][132];   // [k][m], padded (132*4=528B, 16B-aligned rows)
    __shared__ float Bs[16][132];   // [k][n], padded

    int tid = threadIdx.x;
    int m0 = blockIdx.y * 128, n0 = blockIdx.x * 128;
    int ty = tid >> 4, tx = tid & 15;

    // loader mapping
    int aRow = tid >> 1;            // 0..127 (m within tile)
    int aCol = (tid & 1) * 8;       // 0 or 8 (k within tile)
    int bRow = tid >> 4;            // 0..15  (k within tile)
    int bCol = (tid & 15) * 8;      // 0..120 (n within tile)

    const float* Ap = A + (size_t)(m0 + aRow) * K + aCol;
    const bool fast = (n0 + 128 <= N) && ((N & 3) == 0);

    float4 ra0, ra1, rb0, rb1;
    // prefetch tile k0 = 0
    ra0 = *(const float4*)(Ap);
    ra1 = *(const float4*)(Ap + 4);
    if (fast) {
        const float* bp = B + (size_t)bRow * N + n0 + bCol;
        rb0 = *(const float4*)bp;
        rb1 = *(const float4*)(bp + 4);
    } else {
        float t[8];
        #pragma unroll
        for (int j = 0; j < 8; j++) {
            int n = n0 + bCol + j;
            t[j] = (n < N) ? B[(size_t)bRow * N + n] : 0.f;
        }
        rb0 = make_float4(t[0], t[1], t[2], t[3]);
        rb1 = make_float4(t[4], t[5], t[6], t[7]);
    }

    float acc[8][8] = {};

    for (int k0 = 0; k0 < K; k0 += 16) {
        // store prefetched tile to smem (A transposed)
        As[aCol+0][aRow] = ra0.x; As[aCol+1][aRow] = ra0.y;
        As[aCol+2][aRow] = ra0.z; As[aCol+3][aRow] = ra0.w;
        As[aCol+4][aRow] = ra1.x; As[aCol+5][aRow] = ra1.y;
        As[aCol+6][aRow] = ra1.z; As[aCol+7][aRow] = ra1.w;
        *(float4*)&Bs[bRow][bCol]     = rb0;
        *(float4*)&Bs[bRow][bCol + 4] = rb1;
        __syncthreads();

        // prefetch next tile
        if (k0 + 16 < K) {
            ra0 = *(const float4*)(Ap + k0 + 16);
            ra1 = *(const float4*)(Ap + k0 + 20);
            if (fast) {
                const float* bp = B + (size_t)(k0 + 16 + bRow) * N + n0 + bCol;
                rb0 = *(const float4*)bp;
                rb1 = *(const float4*)(bp + 4);
            } else {
                float t[8];
                #pragma unroll
                for (int j = 0; j < 8; j++) {
                    int n = n0 + bCol + j;
                    t[j] = (n < N) ? B[(size_t)(k0 + 16 + bRow) * N + n] : 0.f;
                }
                rb0 = make_float4(t[0], t[1], t[2], t[3]);
                rb1 = make_float4(t[4], t[5], t[6], t[7]);
            }
        }

        // compute
        #pragma unroll
        for (int kk = 0; kk < 16; kk++) {
            float a[8], b[8];
            *(float4*)(a)     = *(const float4*)&As[kk][ty*8];
            *(float4*)(a + 4) = *(const float4*)&As[kk][ty*8 + 4];
            *(float4*)(b)     = *(const float4*)&Bs[kk][tx*8];
            *(float4*)(b + 4) = *(const float4*)&Bs[kk][tx*8 + 4];
            #pragma unroll
            for (int i = 0; i < 8; i++)
                #pragma unroll
                for (int j = 0; j < 8; j++)
                    acc[i][j] = fmaf(a[i], b[j], acc[i][j]);
        }
        __syncthreads();
    }

    // epilogue
    if (fast) {
        #pragma unroll
        for (int i = 0; i < 8; i++) {
            float* cp = C + (size_t)(m0 + ty*8 + i) * N + n0 + tx*8;
            float v[8];
            #pragma unroll
            for (int j = 0; j < 8; j++) {
                float u = acc[i][j];
                if (bias) u += bias[n0 + tx*8 + j];
                if (act == 1) u = gelu_f(u);
                v[j] = u;
            }
            *(float4*)cp       = make_float4(v[0], v[1], v[2], v[3]);
            *(float4*)(cp + 4) = make_float4(v[4], v[5], v[6], v[7]);
        }
    } else {
        #pragma unroll
        for (int i = 0; i < 8; i++) {
            int m = m0 + ty*8 + i;
            #pragma unroll
            for (int j = 0; j < 8; j++) {
                int n = n0 + tx*8 + j;
                if (n < N) {
                    float u = acc[i][j];
                    if (bias) u += bias[n];
                    if (act == 1) u = gelu_f(u);
                    C[(size_t)m * N + n] = u;
                }
            }
        }
    }
}

// ---------------- attention scores: S[bh,i,j] = (Q_i . K_j) / 8 ----------------
// 128x128 output tile per block, K-dim = 64.
__global__ void __launch_bounds__(256, 2)
k_scores(const float* __restrict__ Q, const float* __restrict__ Kv,
         float* __restrict__ Sc)
{
    int bh = blockIdx.z;
    int b = bh / NH, h = bh - b * NH;
    const float* qb = Q  + (size_t)b * SQ * DD + h * DK;
    const float* kb = Kv + (size_t)b * SQ * DD + h * DK;
    float* sb = Sc + (size_t)bh * SQ * SQ;

    int i0 = blockIdx.y * 128, j0 = blockIdx.x * 128;
    __shared__ float Qs[16][132];
    __shared__ float Ks[16][132];

    int tid = threadIdx.x;
    int ty = tid >> 4, tx = tid & 15;
    int aRow = tid >> 1;
    int aCol = (tid & 1) * 8;

    const float* qp = qb + (size_t)(i0 + aRow) * DD + aCol;
    const float* kp = kb + (size_t)(j0 + aRow) * DD + aCol;

    float4 rq0, rq1, rk0, rk1;
    rq0 = *(const float4*)(qp);     rq1 = *(const float4*)(qp + 4);
    rk0 = *(const float4*)(kp);     rk1 = *(const float4*)(kp + 4);

    float acc[8][8] = {};

    for (int k0 = 0; k0 < DK; k0 += 16) {
        Qs[aCol+0][aRow] = rq0.x; Qs[aCol+1][aRow] = rq0.y;
        Qs[aCol+2][aRow] = rq0.z; Qs[aCol+3][aRow] = rq0.w;
        Qs[aCol+4][aRow] = rq1.x; Qs[aCol+5][aRow] = rq1.y;
        Qs[aCol+6][aRow] = rq1.z; Qs[aCol+7][aRow] = rq1.w;
        Ks[aCol+0][aRow] = rk0.x; Ks[aCol+1][aRow] = rk0.y;
        Ks[aCol+2][aRow] = rk0.z; Ks[aCol+3][aRow] = rk0.w;
        Ks[aCol+4][aRow] = rk1.x; Ks[aCol+5][aRow] = rk1.y;
        Ks[aCol+6][aRow] = rk1.z; Ks[aCol+7][aRow] = rk1.w;
        __syncthreads();

        if (k0 + 16 < DK) {
            rq0 = *(const float4*)(qp + k0 + 16);  rq1 = *(const float4*)(qp + k0 + 20);
            rk0 = *(const float4*)(kp + k0 + 16);  rk1 = *(const float4*)(kp + k0 + 20);
        }

        #pragma unroll
        for (int kk = 0; kk < 16; kk++) {
            float a[8], b[8];
            *(float4*)(a)     = *(const float4*)&Qs[kk][ty*8];
            *(float4*)(a + 4) = *(const float4*)&Qs[kk][ty*8 + 4];
            *(float4*)(b)     = *(const float4*)&Ks[kk][tx*8];
            *(float4*)(b + 4) = *(const float4*)&Ks[kk][tx*8 + 4];
            #pragma unroll
            for (int i = 0; i < 8; i++)
                #pragma unroll
                for (int j = 0; j < 8; j++)
                    acc[i][j] = fmaf(a[i], b[j], acc[i][j]);
        }
        __syncthreads();
    }

    const float scale = 0.125f;
    #pragma unroll
    for (int i = 0; i < 8; i++) {
        float* sp = sb + (size_t)(i0 + ty*8 + i) * SQ + j0 + tx*8;
        *(float4*)sp       = make_float4(acc[i][0]*scale, acc[i][1]*scale,
                                         acc[i][2]*scale, acc[i][3]*scale);
        *(float4*)(sp + 4) = make_float4(acc[i][4]*scale, acc[i][5]*scale,
                                         acc[i][6]*scale, acc[i][7]*scale);
    }
}

// ---------------- masked softmax over last dim (row length SQ) ----------------
__global__ void k_softmax(float* __restrict__ Sc, const int* __restrict__ mask)
{
    int r  = blockIdx.x;
    int bh = r / SQ;
    int b  = bh / NH;
    float* row = Sc + (size_t)r * SQ;
    const int* mrow = mask + (size_t)b * SQ;

    int tid = threadIdx.x;
    __shared__ float rbuf[8];

    float v[4];
    float mx = -1e30f;
    #pragma unroll
    for (int j = 0; j < 4; j++) {
        int c = j * 256 + tid;
        float x = row[c];
        if (mrow[c] == 0) x = -1e9f;
        v[j] = x;
        mx = fmaxf(mx, x);
    }
    #pragma unroll
    for (int o = 16; o; o >>= 1) mx = fmaxf(mx, __shfl_xor_sync(0xffffffffu, mx, o));
    __syncthreads();
    if ((tid & 31) == 0) rbuf[tid >> 5] = mx;
    __syncthreads();
    mx = rbuf[0];
    #pragma unroll
    for (int w = 1; w < 8; w++) mx = fmaxf(mx, rbuf[w]);

    float s = 0.f;
    #pragma unroll
    for (int j = 0; j < 4; j++) { v[j] = expf(v[j] - mx); s += v[j]; }
    #pragma unroll
    for (int o = 16; o; o >>= 1) s += __shfl_xor_sync(0xffffffffu, s, o);
    __syncthreads();
    if ((tid & 31) == 0) rbuf[tid >> 5] = s;
    __syncthreads();
    s = rbuf[0];
    #pragma unroll
    for (int w = 1; w < 8; w++) s += rbuf[w];
    float inv = 1.f / s;

    #pragma unroll
    for (int j = 0; j < 4; j++) row[j * 256 + tid] = v[j] * inv;
}

// ---------------- ctx = P @ V (per batch-head), 128x64 tile, 8x8 micro ----------------
__global__ void __launch_bounds__(128)
k_ctx(const float* __restrict__ P, const float* __restrict__ Vv,
      float* __restrict__ C)
{
    int bh = blockIdx.z;
    int b = bh / NH, h = bh - b * NH;
    const float* pb = P  + (size_t)bh * SQ * SQ;
    const float* vb = Vv + (size_t)b * SQ * DD + h * DK;
    float* cb = C + (size_t)b * SQ * DD + h * DK;

    int i0 = blockIdx.y * 128;
    __shared__ float As[16][132];   // [k][i]
    __shared__ float Bs[16][68];    // [k][d], padded (68*4=272B, 16B-aligned)

    int tid = threadIdx.x;
    int ty = tid >> 3, tx = tid & 7;
    int bRow = tid >> 3;            // 0..15
    int bCol = (tid & 7) * 8;       // 0..56

    const float* pp = pb + (size_t)(i0 + tid) * SQ;

    float4 ra0, ra1, ra2, ra3, rb0, rb1;
    ra0 = *(const float4*)(pp);
    ra1 = *(const float4*)(pp + 4);
    ra2 = *(const float4*)(pp + 8);
    ra3 = *(const float4*)(pp + 12);
    {
        const float* bp = vb + (size_t)bRow * DD + bCol;
        rb0 = *(const float4*)bp;
        rb1 = *(const float4*)(bp + 4);
    }

    float acc[8][8] = {};

    for (int k0 = 0; k0 < SQ; k0 += 16) {
        As[0][tid]  = ra0.x; As[1][tid]  = ra0.y; As[2][tid]  = ra0.z; As[3][tid]  = ra0.w;
        As[4][tid]  = ra1.x; As[5][tid]  = ra1.y; As[6][tid]  = ra1.z; As[7][tid]  = ra1.w;
        As[8][tid]  = ra2.x; As[9][tid]  = ra2.y; As[10][tid] = ra2.z; As[11][tid] = ra2.w;
        As[12][tid] = ra3.x; As[13][tid] = ra3.y; As[14][tid] = ra3.z; As[15][tid] = ra3.w;
        *(float4*)&Bs[bRow][bCol]     = rb0;
        *(float4*)&Bs[bRow][bCol + 4] = rb1;
        __syncthreads();

        if (k0 + 16 < SQ) {
            ra0 = *(const float4*)(pp + k0 + 16);
            ra1 = *(const float4*)(pp + k0 + 20);
            ra2 = *(const float4*)(pp + k0 + 24);
            ra3 = *(const float4*)(pp + k0 + 28);
            const float* bp = vb + (size_t)(k0 + 16 + bRow) * DD + bCol;
            rb0 = *(const float4*)bp;
            rb1 = *(const float4*)(bp + 4);
        }

        #pragma unroll
        for (int kk = 0; kk < 16; kk++) {
            float a[8], bb_[8];
            *(float4*)(a)       = *(const float4*)&As[kk][ty*8];
            *(float4*)(a + 4)   = *(const float4*)&As[kk][ty*8 + 4];
            *(float4*)(bb_)     = *(const float4*)&Bs[kk][tx*8];
            *(float4*)(bb_ + 4) = *(const float4*)&Bs[kk][tx*8 + 4];
            #pragma unroll
            for (int i = 0; i < 8; i++)
                #pragma unroll
                for (int j = 0; j < 8; j++)
                    acc[i][j] = fmaf(a[i], bb_[j], acc[i][j]);
        }
        __syncthreads();
    }

    #pragma unroll
    for (int i = 0; i < 8; i++) {
        float* cp = cb + (size_t)(i0 + ty*8 + i) * DD + tx*8;
        *(float4*)cp       = make_float4(acc[i][0], acc[i][1], acc[i][2], acc[i][3]);
        *(float4*)(cp + 4) = make_float4(acc[i][4], acc[i][5], acc[i][6], acc[i][7]);
    }
}

// ---------------- out = LayerNorm(x (+ res)) * g + b ----------------
__global__ void k_addln(const float* __restrict__ X, const float* __restrict__ R,
                        const float* __restrict__ g, const float* __restrict__ bb,
                        float* __restrict__ O)
{
    int r = blockIdx.x;
    const float* xr = X + (size_t)r * DD;
    const float* rr = R ? (R + (size_t)r * DD) : nullptr;
    float* orow = O + (size_t)r * DD;

    int tid = threadIdx.x;
    __shared__ float rbuf[8];

    float v[3];
    float s = 0.f;
    #pragma unroll
    for (int j = 0; j < 3; j++) {
        int c = tid * 3 + j;
        float x = xr[c];
        if (rr) x += rr[c];
        v[j] = x;
        s += x;
    }
    #pragma unroll
    for (int o = 16; o; o >>= 1) s += __shfl_xor_sync(0xffffffffu, s, o);
    __syncthreads();
    if ((tid & 31) == 0) rbuf[tid >> 5] = s;
    __syncthreads();
    s = rbuf[0];
    #pragma unroll
    for (int w = 1; w < 8; w++) s += rbuf[w];
    float mean = s * (1.f / DD);

    float s2 = 0.f;
    #pragma unroll
    for (int j = 0; j < 3; j++) { float d = v[j] - mean; s2 += d * d; }
    #pragma unroll
    for (int o = 16; o; o >>= 1) s2 += __shfl_xor_sync(0xffffffffu, s2, o);
    __syncthreads();
    if ((tid & 31) == 0) rbuf[tid >> 5] = s2;
    __syncthreads();
    s2 = rbuf[0];
    #pragma unroll
    for (int w = 1; w < 8; w++) s2 += rbuf[w];
    float rstd = rsqrtf(s2 * (1.f / DD) + 1e-5f);

    #pragma unroll
    for (int j = 0; j < 3; j++) {
        int c = tid * 3 + j;
        orow[c] = (v[j] - mean) * rstd * g[c] + bb[c];
    }
}

// ---------------- driver ----------------
extern "C" void kernel_launch(void* const* d_in, const int* in_sizes, int n_in,
                              void* d_out, int out_size)
{
    const int*   ids  = (const int*)  d_in[0];
    const int*   mask = (const int*)  d_in[1];
    const float* emb  = (const float*)d_in[2];
    const float* pe   = (const float*)d_in[3];
    const float* Wq   = (const float*)d_in[4];
    const float* Wk   = (const float*)d_in[5];
    const float* Wv   = (const float*)d_in[6];
    const float* Wo   = (const float*)d_in[7];
    const float* ln1g = (const float*)d_in[8];
    const float* ln1b = (const float*)d_in[9];
    const float* ln2g = (const float*)d_in[10];
    const float* ln2b = (const float*)d_in[11];
    const float* W1   = (const float*)d_in[12];
    const float* b1   = (const float*)d_in[13];
    const float* W2   = (const float*)d_in[14];
    const float* b2   = (const float*)d_in[15];
    const float* lnfg = (const float*)d_in[16];
    const float* lnfb = (const float*)d_in[17];
    const float* Wout = (const float*)d_in[18];
    const float* bout = (const float*)d_in[19];
    float* out = (float*)d_out;

    float *x, *q, *k, *v, *ctx, *tmp, *h, *sc;
    cudaGetSymbolAddress((void**)&x,   g_x);
    cudaGetSymbolAddress((void**)&q,   g_q);
    cudaGetSymbolAddress((void**)&k,   g_k);
    cudaGetSymbolAddress((void**)&v,   g_v);
    cudaGetSymbolAddress((void**)&ctx, g_ctx);
    cudaGetSymbolAddress((void**)&tmp, g_tmp);
    cudaGetSymbolAddress((void**)&h,   g_h);
    cudaGetSymbolAddress((void**)&sc,  g_sc);

    k_embed<<<(NT * DD + 255) / 256, 256>>>(ids, emb, pe, x);

    dim3 gD(DD / 128, NT / 128);                 // 6 x 16
    dim3 gF(FF / 128, NT / 128);                 // 24 x 16
    dim3 gV((NV + 127) / 128, NT / 128);         // 393 x 16
    dim3 gS(SQ / 128, SQ / 128, BB * NH);        // 8 x 8 x 24
    dim3 gC(1, SQ / 128, BB * NH);               // 1 x 8 x 24

    for (int l = 0; l < NL; l++) {
        const float* wq = Wq + (size_t)l * DD * DD;
        const float* wk = Wk + (size_t)l * DD * DD;
        const float* wv = Wv + (size_t)l * DD * DD;
        const float* wo = Wo + (size_t)l * DD * DD;

        k_gemm<<<gD, 256>>>(x, wq, nullptr, q, NT, DD, DD, 0);
        k_gemm<<<gD, 256>>>(x, wk, nullptr, k, NT, DD, DD, 0);
        k_gemm<<<gD, 256>>>(x, wv, nullptr, v, NT, DD, DD, 0);

        k_scores <<<gS, 256>>>(q, k, sc);
        k_softmax<<<BB * NH * SQ, 256>>>(sc, mask);
        k_ctx    <<<gC, 128>>>(sc, v, ctx);

        k_gemm<<<gD, 256>>>(ctx, wo, nullptr, tmp, NT, DD, DD, 0);
        k_addln<<<NT, 256>>>(x, tmp, ln1g + (size_t)l * DD, ln1b + (size_t)l * DD, x);

        k_gemm<<<gF, 256>>>(x, W1 + (size_t)l * DD * FF, b1 + (size_t)l * FF, h, NT, FF, DD, 1);
        k_gemm<<<gD, 256>>>(h, W2 + (size_t)l * FF * DD, b2 + (size_t)l * DD, tmp, NT, DD, FF, 0);
        k_addln<<<NT, 256>>>(x, tmp, ln2g + (size_t)l * DD, ln2b + (size_t)l * DD, x);
    }

    k_addln<<<NT, 256>>>(x, nullptr, lnfg, lnfb, x);

    k_gemm<<<gV, 256>>>(x, Wout, bout, out, NT, NV, DD, 0);
}

// round 3
// speedup vs baseline: 2.5472x; 2.2158x over previous
#include <cuda_runtime.h>
#include <math.h>

#define BB 2
#define SQ 1024
#define DD 768
#define NH 12
#define DK 64
#define FF 3072
#define NL 12
#define NV 50257
#define NT (BB*SQ)   // 2048 tokens

// ---------------- scratch (allocation-free: __device__ globals) ----------------
__device__ float g_x  [NT*DD];
__device__ float g_qkv[3*NT*DD];
__device__ float g_ctx[NT*DD];
__device__ float g_tmp[NT*DD];
__device__ float g_h  [NT*FF];
__device__ float g_sc [(size_t)BB*NH*SQ*SQ];   // attention scores, ~100 MB

// ---------------- helpers ----------------
__device__ __forceinline__ unsigned f2tf(float f) {
    unsigned u;
    asm("cvt.rna.tf32.f32 %0, %1;" : "=r"(u) : "f"(f));
    return u;
}
__device__ __forceinline__ float f2tff(float f) { return __uint_as_float(f2tf(f)); }

__device__ __forceinline__ void mma_tf32(float* c, const unsigned* a, const unsigned* b) {
    asm volatile(
        "mma.sync.aligned.m16n8k8.row.col.f32.tf32.tf32.f32 "
        "{%0,%1,%2,%3}, {%4,%5,%6,%7}, {%8,%9}, {%0,%1,%2,%3};"
        : "+f"(c[0]), "+f"(c[1]), "+f"(c[2]), "+f"(c[3])
        : "r"(a[0]), "r"(a[1]), "r"(a[2]), "r"(a[3]), "r"(b[0]), "r"(b[1]));
}

__device__ __forceinline__ float gelu_f(float v) {
    return 0.5f * v * (1.f + erff(v * 0.70710678118654752f));
}

// ---------------- embedding ----------------
__global__ void k_embed(const int* __restrict__ ids, const float* __restrict__ emb,
                        const float* __restrict__ pe, float* __restrict__ x)
{
    int i = blockIdx.x * 256 + threadIdx.x;
    if (i >= NT * DD) return;
    int t = i / DD;
    int d = i - t * DD;
    int s = t % SQ;
    x[i] = emb[(size_t)ids[t] * DD + d] + pe[(size_t)s * DD + d];
}

// =====================================================================
// Generic tf32 MMA GEMM core: C[M,N] = act(A[M,K] @ B[K,N] + bias)
// CTA tile 128x128, BK=16, 256 threads = 8 warps (2m x 4n), warp 64x32.
// A smem [m][k] pad 20 (conflict-free frag loads, vector stores).
// B smem [k][n] pad 136 (conflict-free frag loads, vector stores).
// =====================================================================
__device__ __forceinline__ void gmma_core(
    const float* __restrict__ A, const float* __restrict__ B,
    const float* __restrict__ bias, float* __restrict__ C,
    int N, int K, int act, int m0, int n0,
    float (*As)[20], float (*Bs)[136])
{
    int tid = threadIdx.x;
    int lane = tid & 31, wid = tid >> 5;
    int wm = (wid >> 2) << 6;        // 0 / 64
    int wn = (wid & 3) << 5;         // 0..96
    int g = lane >> 2, tig = lane & 3;

    int aRow = tid >> 1, aCol = (tid & 1) << 3;
    int bRow = tid >> 4, bCol = (tid & 15) << 3;

    const float* Ap = A + (size_t)(m0 + aRow) * K + aCol;
    const bool fast = (n0 + 128 <= N) && ((N & 3) == 0);

    float4 ra0, ra1;
    float rbv[8];
    ra0 = *(const float4*)(Ap);
    ra1 = *(const float4*)(Ap + 4);
    if (fast) {
        const float* bp = B + (size_t)bRow * N + n0 + bCol;
        float4 t0 = *(const float4*)bp, t1 = *(const float4*)(bp + 4);
        rbv[0]=t0.x; rbv[1]=t0.y; rbv[2]=t0.z; rbv[3]=t0.w;
        rbv[4]=t1.x; rbv[5]=t1.y; rbv[6]=t1.z; rbv[7]=t1.w;
    } else {
        #pragma unroll
        for (int j = 0; j < 8; j++) {
            int n = n0 + bCol + j;
            rbv[j] = (n < N) ? B[(size_t)bRow * N + n] : 0.f;
        }
    }

    float acc[4][4][4] = {};

    for (int k0 = 0; k0 < K; k0 += 16) {
        As[aRow][aCol+0] = f2tff(ra0.x); As[aRow][aCol+1] = f2tff(ra0.y);
        As[aRow][aCol+2] = f2tff(ra0.z); As[aRow][aCol+3] = f2tff(ra0.w);
        As[aRow][aCol+4] = f2tff(ra1.x); As[aRow][aCol+5] = f2tff(ra1.y);
        As[aRow][aCol+6] = f2tff(ra1.z); As[aRow][aCol+7] = f2tff(ra1.w);
        #pragma unroll
        for (int j = 0; j < 8; j++) Bs[bRow][bCol + j] = f2tff(rbv[j]);
        __syncthreads();

        if (k0 + 16 < K) {
            ra0 = *(const float4*)(Ap + k0 + 16);
            ra1 = *(const float4*)(Ap + k0 + 20);
            if (fast) {
                const float* bp = B + (size_t)(k0 + 16 + bRow) * N + n0 + bCol;
                float4 t0 = *(const float4*)bp, t1 = *(const float4*)(bp + 4);
                rbv[0]=t0.x; rbv[1]=t0.y; rbv[2]=t0.z; rbv[3]=t0.w;
                rbv[4]=t1.x; rbv[5]=t1.y; rbv[6]=t1.z; rbv[7]=t1.w;
            } else {
                #pragma unroll
                for (int j = 0; j < 8; j++) {
                    int n = n0 + bCol + j;
                    rbv[j] = (n < N) ? B[(size_t)(k0 + 16 + bRow) * N + n] : 0.f;
                }
            }
        }

        #pragma unroll
        for (int kk = 0; kk < 16; kk += 8) {
            unsigned af[4][4], bf[4][2];
            #pragma unroll
            for (int mt = 0; mt < 4; mt++) {
                int r = wm + mt * 16 + g;
                af[mt][0] = __float_as_uint(As[r][kk + tig]);
                af[mt][1] = __float_as_uint(As[r + 8][kk + tig]);
                af[mt][2] = __float_as_uint(As[r][kk + tig + 4]);
                af[mt][3] = __float_as_uint(As[r + 8][kk + tig + 4]);
            }
            #pragma unroll
            for (int nt = 0; nt < 4; nt++) {
                int c = wn + nt * 8 + g;
                bf[nt][0] = __float_as_uint(Bs[kk + tig][c]);
                bf[nt][1] = __float_as_uint(Bs[kk + tig + 4][c]);
            }
            #pragma unroll
            for (int mt = 0; mt < 4; mt++)
                #pragma unroll
                for (int nt = 0; nt < 4; nt++)
                    mma_tf32(acc[mt][nt], af[mt], bf[nt]);
        }
        __syncthreads();
    }

    // epilogue
    #pragma unroll
    for (int mt = 0; mt < 4; mt++) {
        #pragma unroll
        for (int nt = 0; nt < 4; nt++) {
            int row = m0 + wm + mt * 16 + g;
            int col = n0 + wn + nt * 8 + 2 * tig;
            float c0 = acc[mt][nt][0], c1 = acc[mt][nt][1];
            float c2 = acc[mt][nt][2], c3 = acc[mt][nt][3];
            if (fast) {
                float b0 = bias ? bias[col] : 0.f;
                float b1 = bias ? bias[col + 1] : 0.f;
                c0 += b0; c1 += b1; c2 += b0; c3 += b1;
                if (act == 1) { c0 = gelu_f(c0); c1 = gelu_f(c1); c2 = gelu_f(c2); c3 = gelu_f(c3); }
                *(float2*)&C[(size_t)row * N + col]       = make_float2(c0, c1);
                *(float2*)&C[(size_t)(row + 8) * N + col] = make_float2(c2, c3);
            } else {
                if (col < N) {
                    float b0 = bias ? bias[col] : 0.f;
                    float u0 = c0 + b0, u2 = c2 + b0;
                    if (act == 1) { u0 = gelu_f(u0); u2 = gelu_f(u2); }
                    C[(size_t)row * N + col] = u0;
                    C[(size_t)(row + 8) * N + col] = u2;
                }
                if (col + 1 < N) {
                    float b1 = bias ? bias[col + 1] : 0.f;
                    float u1 = c1 + b1, u3 = c3 + b1;
                    if (act == 1) { u1 = gelu_f(u1); u3 = gelu_f(u3); }
                    C[(size_t)row * N + col + 1] = u1;
                    C[(size_t)(row + 8) * N + col + 1] = u3;
                }
            }
        }
    }
}

__global__ void __launch_bounds__(256, 2)
k_gmma(const float* __restrict__ A, const float* __restrict__ B,
       const float* __restrict__ bias, float* __restrict__ C,
       int N, int K, int act)
{
    __shared__ float As[128][20];
    __shared__ float Bs[16][136];
    gmma_core(A, B, bias, C, N, K, act, blockIdx.y * 128, blockIdx.x * 128, As, Bs);
}

// fused QKV: z selects weight matrix + output slab
__global__ void __launch_bounds__(256, 2)
k_qkv(const float* __restrict__ X, const float* __restrict__ Wq,
      const float* __restrict__ Wk, const float* __restrict__ Wv,
      float* __restrict__ QKV)
{
    __shared__ float As[128][20];
    __shared__ float Bs[16][136];
    int z = blockIdx.z;
    const float* W = (z == 0) ? Wq : (z == 1) ? Wk : Wv;
    float* O = QKV + (size_t)z * NT * DD;
    gmma_core(X, W, nullptr, O, DD, DD, 0, blockIdx.y * 128, blockIdx.x * 128, As, Bs);
}

// =====================================================================
// scores: S[bh,i,j] = (Q_i . K_j)/8 — tf32 mma, B transposed layout
// CTA 128x128, K=64. Both tiles stored [row][k] pad 20.
// =====================================================================
__global__ void __launch_bounds__(256, 2)
k_smma(const float* __restrict__ Q, const float* __restrict__ Kv,
       float* __restrict__ Sc)
{
    int bh = blockIdx.z;
    int b = bh / NH, h = bh - b * NH;
    const float* qb = Q  + (size_t)b * SQ * DD + h * DK;
    const float* kb = Kv + (size_t)b * SQ * DD + h * DK;
    float* sb = Sc + (size_t)bh * SQ * SQ;

    int i0 = blockIdx.y * 128, j0 = blockIdx.x * 128;
    __shared__ float Qs[128][20];
    __shared__ float Ks[128][20];

    int tid = threadIdx.x;
    int lane = tid & 31, wid = tid >> 5;
    int wm = (wid >> 2) << 6, wn = (wid & 3) << 5;
    int g = lane >> 2, tig = lane & 3;

    int row = tid >> 1, cc = (tid & 1) << 3;
    const float* qp = qb + (size_t)(i0 + row) * DD + cc;
    const float* kp = kb + (size_t)(j0 + row) * DD + cc;

    float4 rq0, rq1, rk0, rk1;
    rq0 = *(const float4*)(qp);     rq1 = *(const float4*)(qp + 4);
    rk0 = *(const float4*)(kp);     rk1 = *(const float4*)(kp + 4);

    float acc[4][4][4] = {};

    for (int k0 = 0; k0 < DK; k0 += 16) {
        Qs[row][cc+0] = f2tff(rq0.x); Qs[row][cc+1] = f2tff(rq0.y);
        Qs[row][cc+2] = f2tff(rq0.z); Qs[row][cc+3] = f2tff(rq0.w);
        Qs[row][cc+4] = f2tff(rq1.x); Qs[row][cc+5] = f2tff(rq1.y);
        Qs[row][cc+6] = f2tff(rq1.z); Qs[row][cc+7] = f2tff(rq1.w);
        Ks[row][cc+0] = f2tff(rk0.x); Ks[row][cc+1] = f2tff(rk0.y);
        Ks[row][cc+2] = f2tff(rk0.z); Ks[row][cc+3] = f2tff(rk0.w);
        Ks[row][cc+4] = f2tff(rk1.x); Ks[row][cc+5] = f2tff(rk1.y);
        Ks[row][cc+6] = f2tff(rk1.z); Ks[row][cc+7] = f2tff(rk1.w);
        __syncthreads();

        if (k0 + 16 < DK) {
            rq0 = *(const float4*)(qp + k0 + 16);  rq1 = *(const float4*)(qp + k0 + 20);
            rk0 = *(const float4*)(kp + k0 + 16);  rk1 = *(const float4*)(kp + k0 + 20);
        }

        #pragma unroll
        for (int kk = 0; kk < 16; kk += 8) {
            unsigned af[4][4], bf[4][2];
            #pragma unroll
            for (int mt = 0; mt < 4; mt++) {
                int r = wm + mt * 16 + g;
                af[mt][0] = __float_as_uint(Qs[r][kk + tig]);
                af[mt][1] = __float_as_uint(Qs[r + 8][kk + tig]);
                af[mt][2] = __float_as_uint(Qs[r][kk + tig + 4]);
                af[mt][3] = __float_as_uint(Qs[r + 8][kk + tig + 4]);
            }
            #pragma unroll
            for (int nt = 0; nt < 4; nt++) {
                int c = wn + nt * 8 + g;
                bf[nt][0] = __float_as_uint(Ks[c][kk + tig]);
                bf[nt][1] = __float_as_uint(Ks[c][kk + tig + 4]);
            }
            #pragma unroll
            for (int mt = 0; mt < 4; mt++)
                #pragma unroll
                for (int nt = 0; nt < 4; nt++)
                    mma_tf32(acc[mt][nt], af[mt], bf[nt]);
        }
        __syncthreads();
    }

    const float scale = 0.125f;
    #pragma unroll
    for (int mt = 0; mt < 4; mt++)
        #pragma unroll
        for (int nt = 0; nt < 4; nt++) {
            int r = i0 + wm + mt * 16 + g;
            int c = j0 + wn + nt * 8 + 2 * tig;
            *(float2*)&sb[(size_t)r * SQ + c] =
                make_float2(acc[mt][nt][0] * scale, acc[mt][nt][1] * scale);
            *(float2*)&sb[(size_t)(r + 8) * SQ + c] =
                make_float2(acc[mt][nt][2] * scale, acc[mt][nt][3] * scale);
        }
}

// =====================================================================
// ctx = P @ V per batch-head — tf32 mma. CTA 128x64, K=1024.
// =====================================================================
__global__ void __launch_bounds__(256, 2)
k_cmma(const float* __restrict__ P, const float* __restrict__ Vv,
       float* __restrict__ C)
{
    int bh = blockIdx.z;
    int b = bh / NH, h = bh - b * NH;
    const float* pb = P  + (size_t)bh * SQ * SQ;
    const float* vb = Vv + (size_t)b * SQ * DD + h * DK;
    float* cb = C + (size_t)b * SQ * DD + h * DK;

    int i0 = blockIdx.y * 128;
    __shared__ float Ps[128][20];
    __shared__ float Vs[16][72];

    int tid = threadIdx.x;
    int lane = tid & 31, wid = tid >> 5;
    int wm = (wid >> 2) << 6, wn = (wid & 3) << 4;   // warp tile 64 x 16
    int g = lane >> 2, tig = lane & 3;

    int aRow = tid >> 1, aCol = (tid & 1) << 3;
    int bRow = tid >> 4, bCol = (tid & 15) << 2;

    const float* pp = pb + (size_t)(i0 + aRow) * SQ + aCol;

    float4 ra0, ra1, rb;
    ra0 = *(const float4*)(pp);
    ra1 = *(const float4*)(pp + 4);
    rb  = *(const float4*)(vb + (size_t)bRow * DD + bCol);

    float acc[4][2][4] = {};

    for (int k0 = 0; k0 < SQ; k0 += 16) {
        Ps[aRow][aCol+0] = f2tff(ra0.x); Ps[aRow][aCol+1] = f2tff(ra0.y);
        Ps[aRow][aCol+2] = f2tff(ra0.z); Ps[aRow][aCol+3] = f2tff(ra0.w);
        Ps[aRow][aCol+4] = f2tff(ra1.x); Ps[aRow][aCol+5] = f2tff(ra1.y);
        Ps[aRow][aCol+6] = f2tff(ra1.z); Ps[aRow][aCol+7] = f2tff(ra1.w);
        Vs[bRow][bCol+0] = f2tff(rb.x); Vs[bRow][bCol+1] = f2tff(rb.y);
        Vs[bRow][bCol+2] = f2tff(rb.z); Vs[bRow][bCol+3] = f2tff(rb.w);
        __syncthreads();

        if (k0 + 16 < SQ) {
            ra0 = *(const float4*)(pp + k0 + 16);
            ra1 = *(const float4*)(pp + k0 + 20);
            rb  = *(const float4*)(vb + (size_t)(k0 + 16 + bRow) * DD + bCol);
        }

        #pragma unroll
        for (int kk = 0; kk < 16; kk += 8) {
            unsigned af[4][4], bf[2][2];
            #pragma unroll
            for (int mt = 0; mt < 4; mt++) {
                int r = wm + mt * 16 + g;
                af[mt][0] = __float_as_uint(Ps[r][kk + tig]);
                af[mt][1] = __float_as_uint(Ps[r + 8][kk + tig]);
                af[mt][2] = __float_as_uint(Ps[r][kk + tig + 4]);
                af[mt][3] = __float_as_uint(Ps[r + 8][kk + tig + 4]);
            }
            #pragma unroll
            for (int nt = 0; nt < 2; nt++) {
                int c = wn + nt * 8 + g;
                bf[nt][0] = __float_as_uint(Vs[kk + tig][c]);
                bf[nt][1] = __float_as_uint(Vs[kk + tig + 4][c]);
            }
            #pragma unroll
            for (int mt = 0; mt < 4; mt++)
                #pragma unroll
                for (int nt = 0; nt < 2; nt++)
                    mma_tf32(acc[mt][nt], af[mt], bf[nt]);
        }
        __syncthreads();
    }

    #pragma unroll
    for (int mt = 0; mt < 4; mt++)
        #pragma unroll
        for (int nt = 0; nt < 2; nt++) {
            int r = i0 + wm + mt * 16 + g;
            int c = wn + nt * 8 + 2 * tig;
            *(float2*)&cb[(size_t)r * DD + c] =
                make_float2(acc[mt][nt][0], acc[mt][nt][1]);
            *(float2*)&cb[(size_t)(r + 8) * DD + c] =
                make_float2(acc[mt][nt][2], acc[mt][nt][3]);
        }
}

// ---------------- masked softmax over last dim (row length SQ) ----------------
__global__ void k_softmax(float* __restrict__ Sc, const int* __restrict__ mask)
{
    int r  = blockIdx.x;
    int bh = r / SQ;
    int b  = bh / NH;
    float* row = Sc + (size_t)r * SQ;
    const int* mrow = mask + (size_t)b * SQ;

    int tid = threadIdx.x;
    __shared__ float rbuf[8];

    float v[4];
    float mx = -1e30f;
    #pragma unroll
    for (int j = 0; j < 4; j++) {
        int c = j * 256 + tid;
        float x = row[c];
        if (mrow[c] == 0) x = -1e9f;
        v[j] = x;
        mx = fmaxf(mx, x);
    }
    #pragma unroll
    for (int o = 16; o; o >>= 1) mx = fmaxf(mx, __shfl_xor_sync(0xffffffffu, mx, o));
    __syncthreads();
    if ((tid & 31) == 0) rbuf[tid >> 5] = mx;
    __syncthreads();
    mx = rbuf[0];
    #pragma unroll
    for (int w = 1; w < 8; w++) mx = fmaxf(mx, rbuf[w]);

    float s = 0.f;
    #pragma unroll
    for (int j = 0; j < 4; j++) { v[j] = expf(v[j] - mx); s += v[j]; }
    #pragma unroll
    for (int o = 16; o; o >>= 1) s += __shfl_xor_sync(0xffffffffu, s, o);
    __syncthreads();
    if ((tid & 31) == 0) rbuf[tid >> 5] = s;
    __syncthreads();
    s = rbuf[0];
    #pragma unroll
    for (int w = 1; w < 8; w++) s += rbuf[w];
    float inv = 1.f / s;

    #pragma unroll
    for (int j = 0; j < 4; j++) row[j * 256 + tid] = v[j] * inv;
}

// ---------------- out = LayerNorm(x (+ res)) * g + b ----------------
__global__ void k_addln(const float* __restrict__ X, const float* __restrict__ R,
                        const float* __restrict__ g, const float* __restrict__ bb,
                        float* __restrict__ O)
{
    int r = blockIdx.x;
    const float* xr = X + (size_t)r * DD;
    const float* rr = R ? (R + (size_t)r * DD) : nullptr;
    float* orow = O + (size_t)r * DD;

    int tid = threadIdx.x;
    __shared__ float rbuf[8];

    float v[3];
    float s = 0.f;
    #pragma unroll
    for (int j = 0; j < 3; j++) {
        int c = tid * 3 + j;
        float x = xr[c];
        if (rr) x += rr[c];
        v[j] = x;
        s += x;
    }
    #pragma unroll
    for (int o = 16; o; o >>= 1) s += __shfl_xor_sync(0xffffffffu, s, o);
    __syncthreads();
    if ((tid & 31) == 0) rbuf[tid >> 5] = s;
    __syncthreads();
    s = rbuf[0];
    #pragma unroll
    for (int w = 1; w < 8; w++) s += rbuf[w];
    float mean = s * (1.f / DD);

    float s2 = 0.f;
    #pragma unroll
    for (int j = 0; j < 3; j++) { float d = v[j] - mean; s2 += d * d; }
    #pragma unroll
    for (int o = 16; o; o >>= 1) s2 += __shfl_xor_sync(0xffffffffu, s2, o);
    __syncthreads();
    if ((tid & 31) == 0) rbuf[tid >> 5] = s2;
    __syncthreads();
    s2 = rbuf[0];
    #pragma unroll
    for (int w = 1; w < 8; w++) s2 += rbuf[w];
    float rstd = rsqrtf(s2 * (1.f / DD) + 1e-5f);

    #pragma unroll
    for (int j = 0; j < 3; j++) {
        int c = tid * 3 + j;
        orow[c] = (v[j] - mean) * rstd * g[c] + bb[c];
    }
}

// ---------------- driver ----------------
extern "C" void kernel_launch(void* const* d_in, const int* in_sizes, int n_in,
                              void* d_out, int out_size)
{
    const int*   ids  = (const int*)  d_in[0];
    const int*   mask = (const int*)  d_in[1];
    const float* emb  = (const float*)d_in[2];
    const float* pe   = (const float*)d_in[3];
    const float* Wq   = (const float*)d_in[4];
    const float* Wk   = (const float*)d_in[5];
    const float* Wv   = (const float*)d_in[6];
    const float* Wo   = (const float*)d_in[7];
    const float* ln1g = (const float*)d_in[8];
    const float* ln1b = (const float*)d_in[9];
    const float* ln2g = (const float*)d_in[10];
    const float* ln2b = (const float*)d_in[11];
    const float* W1   = (const float*)d_in[12];
    const float* b1   = (const float*)d_in[13];
    const float* W2   = (const float*)d_in[14];
    const float* b2   = (const float*)d_in[15];
    const float* lnfg = (const float*)d_in[16];
    const float* lnfb = (const float*)d_in[17];
    const float* Wout = (const float*)d_in[18];
    const float* bout = (const float*)d_in[19];
    float* out = (float*)d_out;

    float *x, *qkv, *ctx, *tmp, *h, *sc;
    cudaGetSymbolAddress((void**)&x,   g_x);
    cudaGetSymbolAddress((void**)&qkv, g_qkv);
    cudaGetSymbolAddress((void**)&ctx, g_ctx);
    cudaGetSymbolAddress((void**)&tmp, g_tmp);
    cudaGetSymbolAddress((void**)&h,   g_h);
    cudaGetSymbolAddress((void**)&sc,  g_sc);

    float* q = qkv;
    float* k = qkv + (size_t)NT * DD;
    float* v = qkv + (size_t)2 * NT * DD;

    k_embed<<<(NT * DD + 255) / 256, 256>>>(ids, emb, pe, x);

    dim3 gQKV(DD / 128, NT / 128, 3);            // 6 x 16 x 3 = 288
    dim3 gD(DD / 128, NT / 128);                 // 96
    dim3 gF(FF / 128, NT / 128);                 // 384
    dim3 gV((NV + 127) / 128, NT / 128);         // 393 x 16
    dim3 gS(SQ / 128, SQ / 128, BB * NH);        // 8 x 8 x 24
    dim3 gC(1, SQ / 128, BB * NH);               // 1 x 8 x 24

    for (int l = 0; l < NL; l++) {
        const float* wq = Wq + (size_t)l * DD * DD;
        const float* wk = Wk + (size_t)l * DD * DD;
        const float* wv = Wv + (size_t)l * DD * DD;
        const float* wo = Wo + (size_t)l * DD * DD;

        k_qkv<<<gQKV, 256>>>(x, wq, wk, wv, qkv);

        k_smma   <<<gS, 256>>>(q, k, sc);
        k_softmax<<<BB * NH * SQ, 256>>>(sc, mask);
        k_cmma   <<<gC, 256>>>(sc, v, ctx);

        k_gmma<<<gD, 256>>>(ctx, wo, nullptr, tmp, DD, DD, 0);
        k_addln<<<NT, 256>>>(x, tmp, ln1g + (size_t)l * DD, ln1b + (size_t)l * DD, x);

        k_gmma<<<gF, 256>>>(x, W1 + (size_t)l * DD * FF, b1 + (size_t)l * FF, h, FF, DD, 1);
        k_gmma<<<gD, 256>>>(h, W2 + (size_t)l * FF * DD, b2 + (size_t)l * DD, tmp, DD, FF, 0);
        k_addln<<<NT, 256>>>(x, tmp, ln2g + (size_t)l * DD, ln2b + (size_t)l * DD, x);
    }

    k_addln<<<NT, 256>>>(x, nullptr, lnfg, lnfb, x);

    k_gmma<<<gV, 256>>>(x, Wout, bout, out, NV, DD, 0);
}

// round 4
// speedup vs baseline: 2.8388x; 1.1144x over previous
#include <cuda_runtime.h>
#include <math.h>

#define BB 2
#define SQ 1024
#define DD 768
#define NH 12
#define DK 64
#define FF 3072
#define NL 12
#define NV 50257
#define NVP 50432            // NV padded to multiple of 128
#define NT (BB*SQ)           // 2048 tokens

// ---------------- scratch (allocation-free: __device__ globals) ----------------
__device__ float g_x   [NT*DD];
__device__ float g_qkv [3*NT*DD];
__device__ float g_ctx [NT*DD];
__device__ float g_tmp [NT*DD];
__device__ float g_h   [NT*FF];
__device__ float g_wpad[(size_t)DD*NVP];     // padded Wout, ~155 MB

// ---------------- helpers ----------------
__device__ __forceinline__ unsigned f2tf(float f) {
    unsigned u;
    asm("cvt.rna.tf32.f32 %0, %1;" : "=r"(u) : "f"(f));
    return u;
}
__device__ __forceinline__ float f2tff(float f) { return __uint_as_float(f2tf(f)); }

__device__ __forceinline__ void mma_tf32(float* c, const unsigned* a, const unsigned* b) {
    asm volatile(
        "mma.sync.aligned.m16n8k8.row.col.f32.tf32.tf32.f32 "
        "{%0,%1,%2,%3}, {%4,%5,%6,%7}, {%8,%9}, {%0,%1,%2,%3};"
        : "+f"(c[0]), "+f"(c[1]), "+f"(c[2]), "+f"(c[3])
        : "r"(a[0]), "r"(a[1]), "r"(a[2]), "r"(a[3]), "r"(b[0]), "r"(b[1]));
}

__device__ __forceinline__ float gelu_f(float v) {
    return 0.5f * v * (1.f + erff(v * 0.70710678118654752f));
}

// ---------------- embedding ----------------
__global__ void k_embed(const int* __restrict__ ids, const float* __restrict__ emb,
                        const float* __restrict__ pe, float* __restrict__ x)
{
    int i = blockIdx.x * 256 + threadIdx.x;
    if (i >= NT * DD) return;
    int t = i / DD;
    int d = i - t * DD;
    int s = t % SQ;
    x[i] = emb[(size_t)ids[t] * DD + d] + pe[(size_t)s * DD + d];
}

// ---------------- pad Wout into g_wpad ----------------
__global__ void k_padw(const float* __restrict__ W, float* __restrict__ Wp)
{
    long long i = (long long)blockIdx.x * 256 + threadIdx.x;
    if (i >= (long long)DD * NVP) return;
    int k = (int)(i / NVP);
    int n = (int)(i - (long long)k * NVP);
    Wp[i] = (n < NV) ? W[(size_t)k * NV + n] : 0.f;
}

// =====================================================================
// Generic tf32 MMA GEMM core: C[M,N] = act(A[M,K] @ B[K,N] + bias)
// CTA 128x128, BK=16, 256 threads = 8 warps (2m x 4n), warp 64x32.
// =====================================================================
__device__ __forceinline__ void gmma_core(
    const float* __restrict__ A, const float* __restrict__ B,
    const float* __restrict__ bias, float* __restrict__ C,
    int N, int ldb, int K, int act, int m0, int n0,
    float (*As)[20], float (*Bs)[136])
{
    int tid = threadIdx.x;
    int lane = tid & 31, wid = tid >> 5;
    int wm = (wid >> 2) << 6;
    int wn = (wid & 3) << 5;
    int g = lane >> 2, tig = lane & 3;

    int aRow = tid >> 1, aCol = (tid & 1) << 3;
    int bRow = tid >> 4, bCol = (tid & 15) << 3;

    const float* Ap = A + (size_t)(m0 + aRow) * K + aCol;
    const bool fastB = (n0 + 128 <= ldb) && ((ldb & 3) == 0);
    const bool fastC = (n0 + 128 <= N) && ((N & 3) == 0);

    float4 ra0, ra1;
    float rbv[8];
    ra0 = *(const float4*)(Ap);
    ra1 = *(const float4*)(Ap + 4);
    if (fastB) {
        const float* bp = B + (size_t)bRow * ldb + n0 + bCol;
        float4 t0 = *(const float4*)bp, t1 = *(const float4*)(bp + 4);
        rbv[0]=t0.x; rbv[1]=t0.y; rbv[2]=t0.z; rbv[3]=t0.w;
        rbv[4]=t1.x; rbv[5]=t1.y; rbv[6]=t1.z; rbv[7]=t1.w;
    } else {
        #pragma unroll
        for (int j = 0; j < 8; j++) {
            int n = n0 + bCol + j;
            rbv[j] = (n < ldb) ? B[(size_t)bRow * ldb + n] : 0.f;
        }
    }

    float acc[4][4][4] = {};

    for (int k0 = 0; k0 < K; k0 += 16) {
        As[aRow][aCol+0] = f2tff(ra0.x); As[aRow][aCol+1] = f2tff(ra0.y);
        As[aRow][aCol+2] = f2tff(ra0.z); As[aRow][aCol+3] = f2tff(ra0.w);
        As[aRow][aCol+4] = f2tff(ra1.x); As[aRow][aCol+5] = f2tff(ra1.y);
        As[aRow][aCol+6] = f2tff(ra1.z); As[aRow][aCol+7] = f2tff(ra1.w);
        #pragma unroll
        for (int j = 0; j < 8; j++) Bs[bRow][bCol + j] = f2tff(rbv[j]);
        __syncthreads();

        if (k0 + 16 < K) {
            ra0 = *(const float4*)(Ap + k0 + 16);
            ra1 = *(const float4*)(Ap + k0 + 20);
            if (fastB) {
                const float* bp = B + (size_t)(k0 + 16 + bRow) * ldb + n0 + bCol;
                float4 t0 = *(const float4*)bp, t1 = *(const float4*)(bp + 4);
                rbv[0]=t0.x; rbv[1]=t0.y; rbv[2]=t0.z; rbv[3]=t0.w;
                rbv[4]=t1.x; rbv[5]=t1.y; rbv[6]=t1.z; rbv[7]=t1.w;
            } else {
                #pragma unroll
                for (int j = 0; j < 8; j++) {
                    int n = n0 + bCol + j;
                    rbv[j] = (n < ldb) ? B[(size_t)(k0 + 16 + bRow) * ldb + n] : 0.f;
                }
            }
        }

        #pragma unroll
        for (int kk = 0; kk < 16; kk += 8) {
            unsigned af[4][4], bf[4][2];
            #pragma unroll
            for (int mt = 0; mt < 4; mt++) {
                int r = wm + mt * 16 + g;
                af[mt][0] = __float_as_uint(As[r][kk + tig]);
                af[mt][1] = __float_as_uint(As[r + 8][kk + tig]);
                af[mt][2] = __float_as_uint(As[r][kk + tig + 4]);
                af[mt][3] = __float_as_uint(As[r + 8][kk + tig + 4]);
            }
            #pragma unroll
            for (int nt = 0; nt < 4; nt++) {
                int c = wn + nt * 8 + g;
                bf[nt][0] = __float_as_uint(Bs[kk + tig][c]);
                bf[nt][1] = __float_as_uint(Bs[kk + tig + 4][c]);
            }
            #pragma unroll
            for (int mt = 0; mt < 4; mt++)
                #pragma unroll
                for (int nt = 0; nt < 4; nt++)
                    mma_tf32(acc[mt][nt], af[mt], bf[nt]);
        }
        __syncthreads();
    }

    #pragma unroll
    for (int mt = 0; mt < 4; mt++) {
        #pragma unroll
        for (int nt = 0; nt < 4; nt++) {
            int row = m0 + wm + mt * 16 + g;
            int col = n0 + wn + nt * 8 + 2 * tig;
            float c0 = acc[mt][nt][0], c1 = acc[mt][nt][1];
            float c2 = acc[mt][nt][2], c3 = acc[mt][nt][3];
            if (fastC) {
                float b0 = bias ? bias[col] : 0.f;
                float b1 = bias ? bias[col + 1] : 0.f;
                c0 += b0; c1 += b1; c2 += b0; c3 += b1;
                if (act == 1) { c0 = gelu_f(c0); c1 = gelu_f(c1); c2 = gelu_f(c2); c3 = gelu_f(c3); }
                *(float2*)&C[(size_t)row * N + col]       = make_float2(c0, c1);
                *(float2*)&C[(size_t)(row + 8) * N + col] = make_float2(c2, c3);
            } else {
                if (col < N) {
                    float b0 = bias ? bias[col] : 0.f;
                    float u0 = c0 + b0, u2 = c2 + b0;
                    if (act == 1) { u0 = gelu_f(u0); u2 = gelu_f(u2); }
                    C[(size_t)row * N + col] = u0;
                    C[(size_t)(row + 8) * N + col] = u2;
                }
                if (col + 1 < N) {
                    float b1 = bias ? bias[col + 1] : 0.f;
                    float u1 = c1 + b1, u3 = c3 + b1;
                    if (act == 1) { u1 = gelu_f(u1); u3 = gelu_f(u3); }
                    C[(size_t)row * N + col + 1] = u1;
                    C[(size_t)(row + 8) * N + col + 1] = u3;
                }
            }
        }
    }
}

__global__ void __launch_bounds__(256, 2)
k_gmma(const float* __restrict__ A, const float* __restrict__ B,
       const float* __restrict__ bias, float* __restrict__ C,
       int N, int ldb, int K, int act)
{
    __shared__ float As[128][20];
    __shared__ float Bs[16][136];
    gmma_core(A, B, bias, C, N, ldb, K, act, blockIdx.y * 128, blockIdx.x * 128, As, Bs);
}

// m-fastest grid (blockIdx.x = m tile) — vocab GEMM L2 reuse of B across waves
__global__ void __launch_bounds__(256, 2)
k_gmma_m(const float* __restrict__ A, const float* __restrict__ B,
         const float* __restrict__ bias, float* __restrict__ C,
         int N, int ldb, int K, int act)
{
    __shared__ float As[128][20];
    __shared__ float Bs[16][136];
    gmma_core(A, B, bias, C, N, ldb, K, act, blockIdx.x * 128, blockIdx.y * 128, As, Bs);
}

// fused QKV: z selects weight matrix + output slab
__global__ void __launch_bounds__(256, 2)
k_qkv(const float* __restrict__ X, const float* __restrict__ Wq,
      const float* __restrict__ Wk, const float* __restrict__ Wv,
      float* __restrict__ QKV)
{
    __shared__ float As[128][20];
    __shared__ float Bs[16][136];
    int z = blockIdx.z;
    const float* W = (z == 0) ? Wq : (z == 1) ? Wk : Wv;
    float* O = QKV + (size_t)z * NT * DD;
    gmma_core(X, W, nullptr, O, DD, DD, DD, 0, blockIdx.y * 128, blockIdx.x * 128, As, Bs);
}

// =====================================================================
// Flash attention: per CTA = (bh, 128 query rows). 8 warps x 16 rows.
// Loops over 64-key tiles; online softmax; tf32 mma for S and P@V.
// smem pads: A-frag arrays pad 68, V (B-frag by k-row) pad 72.
// =====================================================================
#define FA_SMEM ((128*68 + 64*68 + 64*72 + 128*68 + 64) * 4)

__global__ void __launch_bounds__(256, 1)
k_fattn(const float* __restrict__ Q, const float* __restrict__ K,
        const float* __restrict__ V, const int* __restrict__ mask,
        float* __restrict__ ctx)
{
    extern __shared__ float sm[];
    float* Qs  = sm;                       // [128][68]
    float* Ks  = Qs + 128*68;              // [64][68]
    float* Vs  = Ks + 64*68;               // [64][72]
    float* Ps  = Vs + 64*72;               // [128][68]
    float* msk = Ps + 128*68;              // [64]

    int bh = blockIdx.y;
    int b = bh / NH, h = bh - b * NH;
    int i0 = blockIdx.x * 128;

    const float* qb = Q + (size_t)b * SQ * DD + h * DK;
    const float* kb = K + (size_t)b * SQ * DD + h * DK;
    const float* vb = V + (size_t)b * SQ * DD + h * DK;
    float* cb = ctx + (size_t)b * SQ * DD + h * DK;
    const int* mrow = mask + (size_t)b * SQ;

    int tid = threadIdx.x;
    int lane = tid & 31, w = tid >> 5;
    int g = lane >> 2, tig = lane & 3;
    int wr = w * 16;

    // load Q tile (tf32)
    {
        int r = tid >> 1;
        int c0 = (tid & 1) * 32;
        const float* qp = qb + (size_t)(i0 + r) * DD + c0;
        float* qs = Qs + r * 68 + c0;
        #pragma unroll
        for (int i = 0; i < 8; i++) {
            float4 t = *(const float4*)(qp + 4 * i);
            qs[4*i+0] = f2tff(t.x); qs[4*i+1] = f2tff(t.y);
            qs[4*i+2] = f2tff(t.z); qs[4*i+3] = f2tff(t.w);
        }
    }

    float oacc[8][4] = {};
    float mr0 = -1e30f, mr1 = -1e30f, l0 = 0.f, l1 = 0.f;

    for (int kt = 0; kt < SQ; kt += 64) {
        __syncthreads();   // previous tile's Ks/Vs reads complete
        {
            int r = tid >> 2;
            int c0 = (tid & 3) * 16;
            const float* kp = kb + (size_t)(kt + r) * DD + c0;
            const float* vp = vb + (size_t)(kt + r) * DD + c0;
            float* ks = Ks + r * 68 + c0;
            float* vs = Vs + r * 72 + c0;
            #pragma unroll
            for (int i = 0; i < 4; i++) {
                float4 t = *(const float4*)(kp + 4 * i);
                ks[4*i+0] = f2tff(t.x); ks[4*i+1] = f2tff(t.y);
                ks[4*i+2] = f2tff(t.z); ks[4*i+3] = f2tff(t.w);
                float4 u = *(const float4*)(vp + 4 * i);
                vs[4*i+0] = f2tff(u.x); vs[4*i+1] = f2tff(u.y);
                vs[4*i+2] = f2tff(u.z); vs[4*i+3] = f2tff(u.w);
            }
            if (tid < 64) msk[tid] = (mrow[kt + tid] == 0) ? -1e9f : 0.f;
        }
        __syncthreads();

        // S = Q @ K^T for this warp's 16 rows x 64 keys
        float sacc[8][4] = {};
        #pragma unroll
        for (int kk = 0; kk < 64; kk += 8) {
            unsigned af[4];
            const float* qa = Qs + (wr + g) * 68 + kk + tig;
            af[0] = __float_as_uint(qa[0]);
            af[1] = __float_as_uint(qa[8 * 68]);
            af[2] = __float_as_uint(qa[4]);
            af[3] = __float_as_uint(qa[8 * 68 + 4]);
            #pragma unroll
            for (int j = 0; j < 8; j++) {
                unsigned bf[2];
                const float* kp = Ks + (j * 8 + g) * 68 + kk + tig;
                bf[0] = __float_as_uint(kp[0]);
                bf[1] = __float_as_uint(kp[4]);
                mma_tf32(sacc[j], af, bf);
            }
        }

        // scale + mask + tile row max
        float tm0 = -1e30f, tm1 = -1e30f;
        #pragma unroll
        for (int j = 0; j < 8; j++) {
            int c = j * 8 + 2 * tig;
            float a0 = msk[c], a1 = msk[c + 1];
            sacc[j][0] = sacc[j][0] * 0.125f + a0;
            sacc[j][1] = sacc[j][1] * 0.125f + a1;
            sacc[j][2] = sacc[j][2] * 0.125f + a0;
            sacc[j][3] = sacc[j][3] * 0.125f + a1;
            tm0 = fmaxf(tm0, fmaxf(sacc[j][0], sacc[j][1]));
            tm1 = fmaxf(tm1, fmaxf(sacc[j][2], sacc[j][3]));
        }
        tm0 = fmaxf(tm0, __shfl_xor_sync(0xffffffffu, tm0, 1));
        tm0 = fmaxf(tm0, __shfl_xor_sync(0xffffffffu, tm0, 2));
        tm1 = fmaxf(tm1, __shfl_xor_sync(0xffffffffu, tm1, 1));
        tm1 = fmaxf(tm1, __shfl_xor_sync(0xffffffffu, tm1, 2));

        float mn0 = fmaxf(mr0, tm0), mn1 = fmaxf(mr1, tm1);
        float al0 = __expf(mr0 - mn0), al1 = __expf(mr1 - mn1);

        __syncwarp();   // prior P@V reads (cross-lane) done before overwriting Ps
        float ts0 = 0.f, ts1 = 0.f;
        #pragma unroll
        for (int j = 0; j < 8; j++) {
            float p0 = __expf(sacc[j][0] - mn0);
            float p1 = __expf(sacc[j][1] - mn0);
            float p2 = __expf(sacc[j][2] - mn1);
            float p3 = __expf(sacc[j][3] - mn1);
            ts0 += p0 + p1;
            ts1 += p2 + p3;
            float* pp = Ps + (wr + g) * 68 + j * 8 + 2 * tig;
            pp[0] = f2tff(p0); pp[1] = f2tff(p1);
            pp[8 * 68] = f2tff(p2); pp[8 * 68 + 1] = f2tff(p3);
        }
        ts0 += __shfl_xor_sync(0xffffffffu, ts0, 1);
        ts0 += __shfl_xor_sync(0xffffffffu, ts0, 2);
        ts1 += __shfl_xor_sync(0xffffffffu, ts1, 1);
        ts1 += __shfl_xor_sync(0xffffffffu, ts1, 2);
        l0 = l0 * al0 + ts0;
        l1 = l1 * al1 + ts1;
        mr0 = mn0; mr1 = mn1;

        #pragma unroll
        for (int j = 0; j < 8; j++) {
            oacc[j][0] *= al0; oacc[j][1] *= al0;
            oacc[j][2] *= al1; oacc[j][3] *= al1;
        }
        __syncwarp();   // Ps stores visible to all lanes

        // O += P @ V
        #pragma unroll
        for (int kk = 0; kk < 64; kk += 8) {
            unsigned af[4];
            const float* pa = Ps + (wr + g) * 68 + kk + tig;
            af[0] = __float_as_uint(pa[0]);
            af[1] = __float_as_uint(pa[8 * 68]);
            af[2] = __float_as_uint(pa[4]);
            af[3] = __float_as_uint(pa[8 * 68 + 4]);
            #pragma unroll
            for (int j = 0; j < 8; j++) {
                unsigned bf[2];
                const float* vp = Vs + (kk + tig) * 72 + j * 8 + g;
                bf[0] = __float_as_uint(vp[0]);
                bf[1] = __float_as_uint(vp[4 * 72]);
                mma_tf32(oacc[j], af, bf);
            }
        }
    }

    // finalize: divide by row sums and write ctx
    float il0 = 1.f / l0, il1 = 1.f / l1;
    int r0 = i0 + wr + g;
    #pragma unroll
    for (int j = 0; j < 8; j++) {
        int c = j * 8 + 2 * tig;
        *(float2*)&cb[(size_t)r0 * DD + c] =
            make_float2(oacc[j][0] * il0, oacc[j][1] * il0);
        *(float2*)&cb[(size_t)(r0 + 8) * DD + c] =
            make_float2(oacc[j][2] * il1, oacc[j][3] * il1);
    }
}

// ---------------- out = LayerNorm(x (+ res)) * g + b ----------------
__global__ void k_addln(const float* __restrict__ X, const float* __restrict__ R,
                        const float* __restrict__ g, const float* __restrict__ bb,
                        float* __restrict__ O)
{
    int r = blockIdx.x;
    const float* xr = X + (size_t)r * DD;
    const float* rr = R ? (R + (size_t)r * DD) : nullptr;
    float* orow = O + (size_t)r * DD;

    int tid = threadIdx.x;
    __shared__ float rbuf[8];

    float v[3];
    float s = 0.f;
    #pragma unroll
    for (int j = 0; j < 3; j++) {
        int c = tid * 3 + j;
        float x = xr[c];
        if (rr) x += rr[c];
        v[j] = x;
        s += x;
    }
    #pragma unroll
    for (int o = 16; o; o >>= 1) s += __shfl_xor_sync(0xffffffffu, s, o);
    __syncthreads();
    if ((tid & 31) == 0) rbuf[tid >> 5] = s;
    __syncthreads();
    s = rbuf[0];
    #pragma unroll
    for (int w = 1; w < 8; w++) s += rbuf[w];
    float mean = s * (1.f / DD);

    float s2 = 0.f;
    #pragma unroll
    for (int j = 0; j < 3; j++) { float d = v[j] - mean; s2 += d * d; }
    #pragma unroll
    for (int o = 16; o; o >>= 1) s2 += __shfl_xor_sync(0xffffffffu, s2, o);
    __syncthreads();
    if ((tid & 31) == 0) rbuf[tid >> 5] = s2;
    __syncthreads();
    s2 = rbuf[0];
    #pragma unroll
    for (int w = 1; w < 8; w++) s2 += rbuf[w];
    float rstd = rsqrtf(s2 * (1.f / DD) + 1e-5f);

    #pragma unroll
    for (int j = 0; j < 3; j++) {
        int c = tid * 3 + j;
        orow[c] = (v[j] - mean) * rstd * g[c] + bb[c];
    }
}

// ---------------- driver ----------------
extern "C" void kernel_launch(void* const* d_in, const int* in_sizes, int n_in,
                              void* d_out, int out_size)
{
    const int*   ids  = (const int*)  d_in[0];
    const int*   mask = (const int*)  d_in[1];
    const float* emb  = (const float*)d_in[2];
    const float* pe   = (const float*)d_in[3];
    const float* Wq   = (const float*)d_in[4];
    const float* Wk   = (const float*)d_in[5];
    const float* Wv   = (const float*)d_in[6];
    const float* Wo   = (const float*)d_in[7];
    const float* ln1g = (const float*)d_in[8];
    const float* ln1b = (const float*)d_in[9];
    const float* ln2g = (const float*)d_in[10];
    const float* ln2b = (const float*)d_in[11];
    const float* W1   = (const float*)d_in[12];
    const float* b1   = (const float*)d_in[13];
    const float* W2   = (const float*)d_in[14];
    const float* b2   = (const float*)d_in[15];
    const float* lnfg = (const float*)d_in[16];
    const float* lnfb = (const float*)d_in[17];
    const float* Wout = (const float*)d_in[18];
    const float* bout = (const float*)d_in[19];
    float* out = (float*)d_out;

    float *x, *qkv, *ctx, *tmp, *h, *wpad;
    cudaGetSymbolAddress((void**)&x,    g_x);
    cudaGetSymbolAddress((void**)&qkv,  g_qkv);
    cudaGetSymbolAddress((void**)&ctx,  g_ctx);
    cudaGetSymbolAddress((void**)&tmp,  g_tmp);
    cudaGetSymbolAddress((void**)&h,    g_h);
    cudaGetSymbolAddress((void**)&wpad, g_wpad);

    float* q = qkv;
    float* k = qkv + (size_t)NT * DD;
    float* v = qkv + (size_t)2 * NT * DD;

    cudaFuncSetAttribute(k_fattn, cudaFuncAttributeMaxDynamicSharedMemorySize, FA_SMEM);

    k_embed<<<(NT * DD + 255) / 256, 256>>>(ids, emb, pe, x);
    k_padw<<<(int)(((long long)DD * NVP + 255) / 256), 256>>>(Wout, wpad);

    dim3 gQKV(DD / 128, NT / 128, 3);            // 6 x 16 x 3
    dim3 gD(DD / 128, NT / 128);                 // 96
    dim3 gF(FF / 128, NT / 128);                 // 384
    dim3 gV(NT / 128, NVP / 128);                // m-fastest: 16 x 394? -> 16 x (NVP/128)
    dim3 gA(SQ / 128, BB * NH);                  // 8 x 24

    for (int l = 0; l < NL; l++) {
        const float* wq = Wq + (size_t)l * DD * DD;
        const float* wk = Wk + (size_t)l * DD * DD;
        const float* wv = Wv + (size_t)l * DD * DD;
        const float* wo = Wo + (size_t)l * DD * DD;

        k_qkv<<<gQKV, 256>>>(x, wq, wk, wv, qkv);

        k_fattn<<<gA, 256, FA_SMEM>>>(q, k, v, mask, ctx);

        k_gmma<<<gD, 256>>>(ctx, wo, nullptr, tmp, DD, DD, DD, 0);
        k_addln<<<NT, 256>>>(x, tmp, ln1g + (size_t)l * DD, ln1b + (size_t)l * DD, x);

        k_gmma<<<gF, 256>>>(x, W1 + (size_t)l * DD * FF, b1 + (size_t)l * FF, h, FF, FF, DD, 1);
        k_gmma<<<gD, 256>>>(h, W2 + (size_t)l * FF * DD, b2 + (size_t)l * DD, tmp, DD, DD, FF, 0);
        k_addln<<<NT, 256>>>(x, tmp, ln2g + (size_t)l * DD, ln2b + (size_t)l * DD, x);
    }

    k_addln<<<NT, 256>>>(x, nullptr, lnfg, lnfb, x);

    // vocab projection: padded B (aligned loads), m-fastest grid (L2 B reuse)
    k_gmma_m<<<gV, 256>>>(x, wpad, bout, out, NV, NVP, DD, 0);
}

// round 5
// speedup vs baseline: 2.8594x; 1.0073x over previous
#include <cuda_runtime.h>
#include <math.h>

#define BB 2
#define SQ 1024
#define DD 768
#define NH 12
#define DK 64
#define FF 3072
#define NL 12
#define NV 50257
#define NVP 50432            // NV padded to multiple of 128
#define NT (BB*SQ)           // 2048 tokens

// ---------------- scratch (allocation-free: __device__ globals) ----------------
__device__ float g_x   [NT*DD];
__device__ float g_qkv [3*NT*DD];
__device__ float g_ctx [NT*DD];
__device__ float g_tmp [NT*DD];
__device__ float g_h   [NT*FF];
__device__ float g_wpad[(size_t)DD*NVP];     // padded Wout, ~155 MB

// ---------------- helpers ----------------
__device__ __forceinline__ unsigned f2tf(float f) {
    unsigned u;
    asm("cvt.rna.tf32.f32 %0, %1;" : "=r"(u) : "f"(f));
    return u;
}
__device__ __forceinline__ float f2tff(float f) { return __uint_as_float(f2tf(f)); }

__device__ __forceinline__ void mma_tf32(float* c, const unsigned* a, const unsigned* b) {
    asm volatile(
        "mma.sync.aligned.m16n8k8.row.col.f32.tf32.tf32.f32 "
        "{%0,%1,%2,%3}, {%4,%5,%6,%7}, {%8,%9}, {%0,%1,%2,%3};"
        : "+f"(c[0]), "+f"(c[1]), "+f"(c[2]), "+f"(c[3])
        : "r"(a[0]), "r"(a[1]), "r"(a[2]), "r"(a[3]), "r"(b[0]), "r"(b[1]));
}

__device__ __forceinline__ float gelu_f(float v) {
    return 0.5f * v * (1.f + erff(v * 0.70710678118654752f));
}

// pair-interleave an 8-k block (two float4s) into smem: order k0,k4,k1,k5,k2,k6,k3,k7
__device__ __forceinline__ void st_pair8(float* dst, float4 lo, float4 hi) {
    *(float4*)(dst)     = make_float4(f2tff(lo.x), f2tff(hi.x), f2tff(lo.y), f2tff(hi.y));
    *(float4*)(dst + 4) = make_float4(f2tff(lo.z), f2tff(hi.z), f2tff(lo.w), f2tff(hi.w));
}

// ---------------- embedding ----------------
__global__ void k_embed(const int* __restrict__ ids, const float* __restrict__ emb,
                        const float* __restrict__ pe, float* __restrict__ x)
{
    int i = blockIdx.x * 256 + threadIdx.x;
    if (i >= NT * DD) return;
    int t = i / DD;
    int d = i - t * DD;
    int s = t % SQ;
    x[i] = emb[(size_t)ids[t] * DD + d] + pe[(size_t)s * DD + d];
}

// ---------------- pad Wout into g_wpad ----------------
__global__ void k_padw(const float* __restrict__ W, float* __restrict__ Wp)
{
    long long i = (long long)blockIdx.x * 256 + threadIdx.x;
    if (i >= (long long)DD * NVP) return;
    int k = (int)(i / NVP);
    int n = (int)(i - (long long)k * NVP);
    Wp[i] = (n < NV) ? W[(size_t)k * NV + n] : 0.f;
}

// =====================================================================
// Generic tf32 MMA GEMM core: C[M,N] = act(A[M,K] @ B[K,N] + bias)
// CTA 128x128, BK=16, 256 threads = 8 warps (2m x 4n), warp 64x32.
// A smem pair-interleaved (pad 24) -> LDS.64 fragment loads.
// =====================================================================
__device__ __forceinline__ void gmma_core(
    const float* __restrict__ A, const float* __restrict__ B,
    const float* __restrict__ bias, float* __restrict__ C,
    int N, int ldb, int K, int act, int m0, int n0,
    float (*As)[24], float (*Bs)[136])
{
    int tid = threadIdx.x;
    int lane = tid & 31, wid = tid >> 5;
    int wm = (wid >> 2) << 6;
    int wn = (wid & 3) << 5;
    int g = lane >> 2, tig = lane & 3;

    int aRow = tid >> 1, aCol = (tid & 1) << 3;
    int bRow = tid >> 4, bCol = (tid & 15) << 3;

    const float* Ap = A + (size_t)(m0 + aRow) * K + aCol;
    const bool fastB = (n0 + 128 <= ldb) && ((ldb & 3) == 0);
    const bool fastC = (n0 + 128 <= N) && ((N & 3) == 0);

    float4 ra0, ra1;
    float rbv[8];
    ra0 = *(const float4*)(Ap);
    ra1 = *(const float4*)(Ap + 4);
    if (fastB) {
        const float* bp = B + (size_t)bRow * ldb + n0 + bCol;
        float4 t0 = *(const float4*)bp, t1 = *(const float4*)(bp + 4);
        rbv[0]=t0.x; rbv[1]=t0.y; rbv[2]=t0.z; rbv[3]=t0.w;
        rbv[4]=t1.x; rbv[5]=t1.y; rbv[6]=t1.z; rbv[7]=t1.w;
    } else {
        #pragma unroll
        for (int j = 0; j < 8; j++) {
            int n = n0 + bCol + j;
            rbv[j] = (n < ldb) ? B[(size_t)bRow * ldb + n] : 0.f;
        }
    }

    float acc[4][4][4] = {};

    for (int k0 = 0; k0 < K; k0 += 16) {
        st_pair8(&As[aRow][aCol], ra0, ra1);
        #pragma unroll
        for (int j = 0; j < 8; j++) Bs[bRow][bCol + j] = f2tff(rbv[j]);
        __syncthreads();

        if (k0 + 16 < K) {
            ra0 = *(const float4*)(Ap + k0 + 16);
            ra1 = *(const float4*)(Ap + k0 + 20);
            if (fastB) {
                const float* bp = B + (size_t)(k0 + 16 + bRow) * ldb + n0 + bCol;
                float4 t0 = *(const float4*)bp, t1 = *(const float4*)(bp + 4);
                rbv[0]=t0.x; rbv[1]=t0.y; rbv[2]=t0.z; rbv[3]=t0.w;
                rbv[4]=t1.x; rbv[5]=t1.y; rbv[6]=t1.z; rbv[7]=t1.w;
            } else {
                #pragma unroll
                for (int j = 0; j < 8; j++) {
                    int n = n0 + bCol + j;
                    rbv[j] = (n < ldb) ? B[(size_t)(k0 + 16 + bRow) * ldb + n] : 0.f;
                }
            }
        }

        #pragma unroll
        for (int kk = 0; kk < 16; kk += 8) {
            unsigned af[4][4], bf[4][2];
            #pragma unroll
            for (int mt = 0; mt < 4; mt++) {
                int r = wm + mt * 16 + g;
                float2 pa = *(const float2*)&As[r][kk + 2 * tig];
                float2 pb = *(const float2*)&As[r + 8][kk + 2 * tig];
                af[mt][0] = __float_as_uint(pa.x);
                af[mt][1] = __float_as_uint(pb.x);
                af[mt][2] = __float_as_uint(pa.y);
                af[mt][3] = __float_as_uint(pb.y);
            }
            #pragma unroll
            for (int nt = 0; nt < 4; nt++) {
                int c = wn + nt * 8 + g;
                bf[nt][0] = __float_as_uint(Bs[kk + tig][c]);
                bf[nt][1] = __float_as_uint(Bs[kk + tig + 4][c]);
            }
            #pragma unroll
            for (int mt = 0; mt < 4; mt++)
                #pragma unroll
                for (int nt = 0; nt < 4; nt++)
                    mma_tf32(acc[mt][nt], af[mt], bf[nt]);
        }
        __syncthreads();
    }

    #pragma unroll
    for (int mt = 0; mt < 4; mt++) {
        #pragma unroll
        for (int nt = 0; nt < 4; nt++) {
            int row = m0 + wm + mt * 16 + g;
            int col = n0 + wn + nt * 8 + 2 * tig;
            float c0 = acc[mt][nt][0], c1 = acc[mt][nt][1];
            float c2 = acc[mt][nt][2], c3 = acc[mt][nt][3];
            if (fastC) {
                float b0 = bias ? bias[col] : 0.f;
                float b1 = bias ? bias[col + 1] : 0.f;
                c0 += b0; c1 += b1; c2 += b0; c3 += b1;
                if (act == 1) { c0 = gelu_f(c0); c1 = gelu_f(c1); c2 = gelu_f(c2); c3 = gelu_f(c3); }
                *(float2*)&C[(size_t)row * N + col]       = make_float2(c0, c1);
                *(float2*)&C[(size_t)(row + 8) * N + col] = make_float2(c2, c3);
            } else {
                if (col < N) {
                    float b0 = bias ? bias[col] : 0.f;
                    float u0 = c0 + b0, u2 = c2 + b0;
                    if (act == 1) { u0 = gelu_f(u0); u2 = gelu_f(u2); }
                    C[(size_t)row * N + col] = u0;
                    C[(size_t)(row + 8) * N + col] = u2;
                }
                if (col + 1 < N) {
                    float b1 = bias ? bias[col + 1] : 0.f;
                    float u1 = c1 + b1, u3 = c3 + b1;
                    if (act == 1) { u1 = gelu_f(u1); u3 = gelu_f(u3); }
                    C[(size_t)row * N + col + 1] = u1;
                    C[(size_t)(row + 8) * N + col + 1] = u3;
                }
            }
        }
    }
}

__global__ void __launch_bounds__(256, 2)
k_gmma(const float* __restrict__ A, const float* __restrict__ B,
       const float* __restrict__ bias, float* __restrict__ C,
       int N, int ldb, int K, int act)
{
    __shared__ float As[128][24];
    __shared__ float Bs[16][136];
    gmma_core(A, B, bias, C, N, ldb, K, act, blockIdx.y * 128, blockIdx.x * 128, As, Bs);
}

// m-fastest grid — vocab GEMM L2 reuse of B across waves
__global__ void __launch_bounds__(256, 2)
k_gmma_m(const float* __restrict__ A, const float* __restrict__ B,
         const float* __restrict__ bias, float* __restrict__ C,
         int N, int ldb, int K, int act)
{
    __shared__ float As[128][24];
    __shared__ float Bs[16][136];
    gmma_core(A, B, bias, C, N, ldb, K, act, blockIdx.x * 128, blockIdx.y * 128, As, Bs);
}

// fused QKV
__global__ void __launch_bounds__(256, 2)
k_qkv(const float* __restrict__ X, const float* __restrict__ Wq,
      const float* __restrict__ Wk, const float* __restrict__ Wv,
      float* __restrict__ QKV)
{
    __shared__ float As[128][24];
    __shared__ float Bs[16][136];
    int z = blockIdx.z;
    const float* W = (z == 0) ? Wq : (z == 1) ? Wk : Wv;
    float* O = QKV + (size_t)z * NT * DD;
    gmma_core(X, W, nullptr, O, DD, DD, DD, 0, blockIdx.y * 128, blockIdx.x * 128, As, Bs);
}

// =====================================================================
// Flash attention v2: CTA = (bh, 128 q rows); key tile 128; 8 warps x 16 rows.
// Qs/Ks pair-interleaved over dk (pad 72); Ps pair-interleaved over keys (pad 136);
// Vs plain [k][d] pad 72.
// =====================================================================
#define FA_SMEM ((128*72*3 + 128*136 + 128) * 4)

__global__ void __launch_bounds__(256, 1)
k_fattn(const float* __restrict__ Q, const float* __restrict__ K,
        const float* __restrict__ V, const int* __restrict__ mask,
        float* __restrict__ ctx)
{
    extern __shared__ float sm[];
    float* Qs  = sm;                        // [128][72] pair-interleaved dk
    float* Ks  = Qs + 128*72;               // [128][72] pair-interleaved dk
    float* Vs  = Ks + 128*72;               // [128][72] plain [k][d]
    float* Ps  = Vs + 128*72;               // [128][136] pair-interleaved keys
    float* msk = Ps + 128*136;              // [128]

    int bh = blockIdx.y;
    int b = bh / NH, h = bh - b * NH;
    int i0 = blockIdx.x * 128;

    const float* qb = Q + (size_t)b * SQ * DD + h * DK;
    const float* kb = K + (size_t)b * SQ * DD + h * DK;
    const float* vb = V + (size_t)b * SQ * DD + h * DK;
    float* cb = ctx + (size_t)b * SQ * DD + h * DK;
    const int* mrow = mask + (size_t)b * SQ;

    int tid = threadIdx.x;
    int lane = tid & 31, w = tid >> 5;
    int g = lane >> 2, tig = lane & 3;
    int wr = w * 16;

    // load Q tile, pair-interleaved
    {
        int r = tid >> 1;
        int c0 = (tid & 1) * 32;
        const float* qp = qb + (size_t)(i0 + r) * DD + c0;
        float* qs = Qs + r * 72 + c0;
        #pragma unroll
        for (int i = 0; i < 4; i++) {
            float4 lo = *(const float4*)(qp + 8 * i);
            float4 hi = *(const float4*)(qp + 8 * i + 4);
            st_pair8(qs + 8 * i, lo, hi);
        }
    }

    // P store positions for this thread's frag columns
    int p0 = (tig < 2) ? 4 * tig : 4 * (tig - 2) + 1;   // key j*8+2tig
    // key j*8+2tig+1 -> p0+2

    float oacc[8][4] = {};
    float mr0 = -1e30f, mr1 = -1e30f, l0 = 0.f, l1 = 0.f;

    for (int kt = 0; kt < SQ; kt += 128) {
        __syncthreads();   // previous tile reads done
        {
            int r = tid >> 1;
            int c0 = (tid & 1) * 32;
            const float* kp = kb + (size_t)(kt + r) * DD + c0;
            const float* vp = vb + (size_t)(kt + r) * DD + c0;
            float* ks = Ks + r * 72 + c0;
            float* vs = Vs + r * 72 + c0;
            #pragma unroll
            for (int i = 0; i < 4; i++) {
                float4 lo = *(const float4*)(kp + 8 * i);
                float4 hi = *(const float4*)(kp + 8 * i + 4);
                st_pair8(ks + 8 * i, lo, hi);
                float4 v0 = *(const float4*)(vp + 8 * i);
                float4 v1 = *(const float4*)(vp + 8 * i + 4);
                *(float4*)(vs + 8*i)     = make_float4(f2tff(v0.x), f2tff(v0.y), f2tff(v0.z), f2tff(v0.w));
                *(float4*)(vs + 8*i + 4) = make_float4(f2tff(v1.x), f2tff(v1.y), f2tff(v1.z), f2tff(v1.w));
            }
            if (tid < 128) msk[tid] = (mrow[kt + tid] == 0) ? -1e9f : 0.f;
        }
        __syncthreads();

        // S = Q @ K^T : 16 rows x 128 keys per warp
        float sacc[16][4] = {};
        #pragma unroll
        for (int kk = 0; kk < DK; kk += 8) {
            unsigned af[4];
            {
                float2 pa = *(const float2*)(Qs + (wr + g) * 72 + kk + 2 * tig);
                float2 pb = *(const float2*)(Qs + (wr + g + 8) * 72 + kk + 2 * tig);
                af[0] = __float_as_uint(pa.x); af[1] = __float_as_uint(pb.x);
                af[2] = __float_as_uint(pa.y); af[3] = __float_as_uint(pb.y);
            }
            #pragma unroll
            for (int j = 0; j < 16; j++) {
                unsigned bf[2];
                float2 pk = *(const float2*)(Ks + (j * 8 + g) * 72 + kk + 2 * tig);
                bf[0] = __float_as_uint(pk.x);
                bf[1] = __float_as_uint(pk.y);
                mma_tf32(sacc[j], af, bf);
            }
        }

        // scale + mask + tile row max
        float tm0 = -1e30f, tm1 = -1e30f;
        #pragma unroll
        for (int j = 0; j < 16; j++) {
            int c = j * 8 + 2 * tig;
            float a0 = msk[c], a1 = msk[c + 1];
            sacc[j][0] = sacc[j][0] * 0.125f + a0;
            sacc[j][1] = sacc[j][1] * 0.125f + a1;
            sacc[j][2] = sacc[j][2] * 0.125f + a0;
            sacc[j][3] = sacc[j][3] * 0.125f + a1;
            tm0 = fmaxf(tm0, fmaxf(sacc[j][0], sacc[j][1]));
            tm1 = fmaxf(tm1, fmaxf(sacc[j][2], sacc[j][3]));
        }
        tm0 = fmaxf(tm0, __shfl_xor_sync(0xffffffffu, tm0, 1));
        tm0 = fmaxf(tm0, __shfl_xor_sync(0xffffffffu, tm0, 2));
        tm1 = fmaxf(tm1, __shfl_xor_sync(0xffffffffu, tm1, 1));
        tm1 = fmaxf(tm1, __shfl_xor_sync(0xffffffffu, tm1, 2));

        float mn0 = fmaxf(mr0, tm0), mn1 = fmaxf(mr1, tm1);
        float al0 = __expf(mr0 - mn0), al1 = __expf(mr1 - mn1);

        __syncwarp();   // prior P@V reads done before overwriting Ps
        float ts0 = 0.f, ts1 = 0.f;
        #pragma unroll
        for (int j = 0; j < 16; j++) {
            float p0v = __expf(sacc[j][0] - mn0);
            float p1v = __expf(sacc[j][1] - mn0);
            float p2v = __expf(sacc[j][2] - mn1);
            float p3v = __expf(sacc[j][3] - mn1);
            ts0 += p0v + p1v;
            ts1 += p2v + p3v;
            float* pr0 = Ps + (wr + g) * 136 + j * 8;
            float* pr1 = Ps + (wr + g + 8) * 136 + j * 8;
            pr0[p0]     = f2tff(p0v);
            pr0[p0 + 2] = f2tff(p1v);
            pr1[p0]     = f2tff(p2v);
            pr1[p0 + 2] = f2tff(p3v);
        }
        ts0 += __shfl_xor_sync(0xffffffffu, ts0, 1);
        ts0 += __shfl_xor_sync(0xffffffffu, ts0, 2);
        ts1 += __shfl_xor_sync(0xffffffffu, ts1, 1);
        ts1 += __shfl_xor_sync(0xffffffffu, ts1, 2);
        l0 = l0 * al0 + ts0;
        l1 = l1 * al1 + ts1;
        mr0 = mn0; mr1 = mn1;

        #pragma unroll
        for (int j = 0; j < 8; j++) {
            oacc[j][0] *= al0; oacc[j][1] *= al0;
            oacc[j][2] *= al1; oacc[j][3] *= al1;
        }
        __syncwarp();   // Ps stores visible within warp

        // O += P @ V (keys 0..128, d cols 0..64)
        #pragma unroll
        for (int kk = 0; kk < 128; kk += 8) {
            unsigned af[4];
            {
                float2 pa = *(const float2*)(Ps + (wr + g) * 136 + kk + 2 * tig);
                float2 pb = *(const float2*)(Ps + (wr + g + 8) * 136 + kk + 2 * tig);
                af[0] = __float_as_uint(pa.x); af[1] = __float_as_uint(pb.x);
                af[2] = __float_as_uint(pa.y); af[3] = __float_as_uint(pb.y);
            }
            #pragma unroll
            for (int j = 0; j < 8; j++) {
                unsigned bf[2];
                const float* vp = Vs + (kk + tig) * 72 + j * 8 + g;
                bf[0] = __float_as_uint(vp[0]);
                bf[1] = __float_as_uint(vp[4 * 72]);
                mma_tf32(oacc[j], af, bf);
            }
        }
    }

    float il0 = 1.f / l0, il1 = 1.f / l1;
    int r0 = i0 + wr + g;
    #pragma unroll
    for (int j = 0; j < 8; j++) {
        int c = j * 8 + 2 * tig;
        *(float2*)&cb[(size_t)r0 * DD + c] =
            make_float2(oacc[j][0] * il0, oacc[j][1] * il0);
        *(float2*)&cb[(size_t)(r0 + 8) * DD + c] =
            make_float2(oacc[j][2] * il1, oacc[j][3] * il1);
    }
}

// ---------------- out = LayerNorm(x (+ res)) * g + b ----------------
__global__ void k_addln(const float* __restrict__ X, const float* __restrict__ R,
                        const float* __restrict__ g, const float* __restrict__ bb,
                        float* __restrict__ O)
{
    int r = blockIdx.x;
    const float* xr = X + (size_t)r * DD;
    const float* rr = R ? (R + (size_t)r * DD) : nullptr;
    float* orow = O + (size_t)r * DD;

    int tid = threadIdx.x;
    __shared__ float rbuf[8];

    float v[3];
    float s = 0.f;
    #pragma unroll
    for (int j = 0; j < 3; j++) {
        int c = tid * 3 + j;
        float x = xr[c];
        if (rr) x += rr[c];
        v[j] = x;
        s += x;
    }
    #pragma unroll
    for (int o = 16; o; o >>= 1) s += __shfl_xor_sync(0xffffffffu, s, o);
    __syncthreads();
    if ((tid & 31) == 0) rbuf[tid >> 5] = s;
    __syncthreads();
    s = rbuf[0];
    #pragma unroll
    for (int w = 1; w < 8; w++) s += rbuf[w];
    float mean = s * (1.f / DD);

    float s2 = 0.f;
    #pragma unroll
    for (int j = 0; j < 3; j++) { float d = v[j] - mean; s2 += d * d; }
    #pragma unroll
    for (int o = 16; o; o >>= 1) s2 += __shfl_xor_sync(0xffffffffu, s2, o);
    __syncthreads();
    if ((tid & 31) == 0) rbuf[tid >> 5] = s2;
    __syncthreads();
    s2 = rbuf[0];
    #pragma unroll
    for (int w = 1; w < 8; w++) s2 += rbuf[w];
    float rstd = rsqrtf(s2 * (1.f / DD) + 1e-5f);

    #pragma unroll
    for (int j = 0; j < 3; j++) {
        int c = tid * 3 + j;
        orow[c] = (v[j] - mean) * rstd * g[c] + bb[c];
    }
}

// ---------------- driver ----------------
extern "C" void kernel_launch(void* const* d_in, const int* in_sizes, int n_in,
                              void* d_out, int out_size)
{
    const int*   ids  = (const int*)  d_in[0];
    const int*   mask = (const int*)  d_in[1];
    const float* emb  = (const float*)d_in[2];
    const float* pe   = (const float*)d_in[3];
    const float* Wq   = (const float*)d_in[4];
    const float* Wk   = (const float*)d_in[5];
    const float* Wv   = (const float*)d_in[6];
    const float* Wo   = (const float*)d_in[7];
    const float* ln1g = (const float*)d_in[8];
    const float* ln1b = (const float*)d_in[9];
    const float* ln2g = (const float*)d_in[10];
    const float* ln2b = (const float*)d_in[11];
    const float* W1   = (const float*)d_in[12];
    const float* b1   = (const float*)d_in[13];
    const float* W2   = (const float*)d_in[14];
    const float* b2   = (const float*)d_in[15];
    const float* lnfg = (const float*)d_in[16];
    const float* lnfb = (const float*)d_in[17];
    const float* Wout = (const float*)d_in[18];
    const float* bout = (const float*)d_in[19];
    float* out = (float*)d_out;

    float *x, *qkv, *ctx, *tmp, *h, *wpad;
    cudaGetSymbolAddress((void**)&x,    g_x);
    cudaGetSymbolAddress((void**)&qkv,  g_qkv);
    cudaGetSymbolAddress((void**)&ctx,  g_ctx);
    cudaGetSymbolAddress((void**)&tmp,  g_tmp);
    cudaGetSymbolAddress((void**)&h,    g_h);
    cudaGetSymbolAddress((void**)&wpad, g_wpad);

    float* q = qkv;
    float* k = qkv + (size_t)NT * DD;
    float* v = qkv + (size_t)2 * NT * DD;

    cudaFuncSetAttribute(k_fattn, cudaFuncAttributeMaxDynamicSharedMemorySize, FA_SMEM);

    k_embed<<<(NT * DD + 255) / 256, 256>>>(ids, emb, pe, x);
    k_padw<<<(int)(((long long)DD * NVP + 255) / 256), 256>>>(Wout, wpad);

    dim3 gQKV(DD / 128, NT / 128, 3);
    dim3 gD(DD / 128, NT / 128);
    dim3 gF(FF / 128, NT / 128);
    dim3 gV(NT / 128, NVP / 128);
    dim3 gA(SQ / 128, BB * NH);

    for (int l = 0; l < NL; l++) {
        const float* wq = Wq + (size_t)l * DD * DD;
        const float* wk = Wk + (size_t)l * DD * DD;
        const float* wv = Wv + (size_t)l * DD * DD;
        const float* wo = Wo + (size_t)l * DD * DD;

        k_qkv<<<gQKV, 256>>>(x, wq, wk, wv, qkv);

        k_fattn<<<gA, 256, FA_SMEM>>>(q, k, v, mask, ctx);

        k_gmma<<<gD, 256>>>(ctx, wo, nullptr, tmp, DD, DD, DD, 0);
        k_addln<<<NT, 256>>>(x, tmp, ln1g + (size_t)l * DD, ln1b + (size_t)l * DD, x);

        k_gmma<<<gF, 256>>>(x, W1 + (size_t)l * DD * FF, b1 + (size_t)l * FF, h, FF, FF, DD, 1);
        k_gmma<<<gD, 256>>>(h, W2 + (size_t)l * FF * DD, b2 + (size_t)l * DD, tmp, DD, DD, FF, 0);
        k_addln<<<NT, 256>>>(x, tmp, ln2g + (size_t)l * DD, ln2b + (size_t)l * DD, x);
    }

    k_addln<<<NT, 256>>>(x, nullptr, lnfg, lnfb, x);

    k_gmma_m<<<gV, 256>>>(x, wpad, bout, out, NV, NVP, DD, 0);
}

// round 6
// speedup vs baseline: 2.9431x; 1.0293x over previous
#include <cuda_runtime.h>
#include <math.h>

#define BB 2
#define SQ 1024
#define DD 768
#define NH 12
#define DK 64
#define FF 3072
#define NL 12
#define NV 50257
#define NVP 50432            // NV padded to multiple of 128
#define NT (BB*SQ)           // 2048 tokens

// ---------------- scratch (allocation-free: __device__ globals) ----------------
__device__ float g_x   [NT*DD];
__device__ float g_qkv [3*NT*DD];
__device__ float g_ctx [NT*DD];
__device__ float g_tmp [NT*DD];
__device__ float g_h   [NT*FF];
__device__ float g_wpad[(size_t)DD*NVP];     // padded Wout, ~155 MB

// ---------------- helpers ----------------
__device__ __forceinline__ unsigned f2tf(float f) {
    unsigned u;
    asm("cvt.rna.tf32.f32 %0, %1;" : "=r"(u) : "f"(f));
    return u;
}
__device__ __forceinline__ float f2tff(float f) { return __uint_as_float(f2tf(f)); }

__device__ __forceinline__ void mma_tf32(float* c, const unsigned* a, const unsigned* b) {
    asm volatile(
        "mma.sync.aligned.m16n8k8.row.col.f32.tf32.tf32.f32 "
        "{%0,%1,%2,%3}, {%4,%5,%6,%7}, {%8,%9}, {%0,%1,%2,%3};"
        : "+f"(c[0]), "+f"(c[1]), "+f"(c[2]), "+f"(c[3])
        : "r"(a[0]), "r"(a[1]), "r"(a[2]), "r"(a[3]), "r"(b[0]), "r"(b[1]));
}

__device__ __forceinline__ float gelu_f(float v) {
    return 0.5f * v * (1.f + erff(v * 0.70710678118654752f));
}

// pair-interleave an 8-k block (two float4s) into smem: order k0,k4,k1,k5,k2,k6,k3,k7
__device__ __forceinline__ void st_pair8(float* dst, float4 lo, float4 hi) {
    *(float4*)(dst)     = make_float4(f2tff(lo.x), f2tff(hi.x), f2tff(lo.y), f2tff(hi.y));
    *(float4*)(dst + 4) = make_float4(f2tff(lo.z), f2tff(hi.z), f2tff(lo.w), f2tff(hi.w));
}

// ---------------- embedding ----------------
__global__ void k_embed(const int* __restrict__ ids, const float* __restrict__ emb,
                        const float* __restrict__ pe, float* __restrict__ x)
{
    int i = blockIdx.x * 256 + threadIdx.x;
    if (i >= NT * DD) return;
    int t = i / DD;
    int d = i - t * DD;
    int s = t % SQ;
    x[i] = emb[(size_t)ids[t] * DD + d] + pe[(size_t)s * DD + d];
}

// ---------------- pad Wout into g_wpad ----------------
__global__ void k_padw(const float* __restrict__ W, float* __restrict__ Wp)
{
    long long i = (long long)blockIdx.x * 256 + threadIdx.x;
    if (i >= (long long)DD * NVP) return;
    int k = (int)(i / NVP);
    int n = (int)(i - (long long)k * NVP);
    Wp[i] = (n < NV) ? W[(size_t)k * NV + n] : 0.f;
}

// =====================================================================
// Generic tf32 MMA GEMM core: C[M,N] = act(A[M,K] @ B[K,N] + bias)
// CTA 128x128, BK=16, 256 threads = 8 warps (2m x 4n), warp 64x32.
// A smem pair-interleaved (pad 24) -> LDS.64 fragment loads.
// =====================================================================
__device__ __forceinline__ void gmma_core(
    const float* __restrict__ A, const float* __restrict__ B,
    const float* __restrict__ bias, float* __restrict__ C,
    int N, int ldb, int K, int act, int m0, int n0,
    float (*As)[24], float (*Bs)[136])
{
    int tid = threadIdx.x;
    int lane = tid & 31, wid = tid >> 5;
    int wm = (wid >> 2) << 6;
    int wn = (wid & 3) << 5;
    int g = lane >> 2, tig = lane & 3;

    int aRow = tid >> 1, aCol = (tid & 1) << 3;
    int bRow = tid >> 4, bCol = (tid & 15) << 3;

    const float* Ap = A + (size_t)(m0 + aRow) * K + aCol;
    const bool fastB = (n0 + 128 <= ldb) && ((ldb & 3) == 0);
    const bool fastC = (n0 + 128 <= N) && ((N & 3) == 0);

    float4 ra0, ra1;
    float rbv[8];
    ra0 = *(const float4*)(Ap);
    ra1 = *(const float4*)(Ap + 4);
    if (fastB) {
        const float* bp = B + (size_t)bRow * ldb + n0 + bCol;
        float4 t0 = *(const float4*)bp, t1 = *(const float4*)(bp + 4);
        rbv[0]=t0.x; rbv[1]=t0.y; rbv[2]=t0.z; rbv[3]=t0.w;
        rbv[4]=t1.x; rbv[5]=t1.y; rbv[6]=t1.z; rbv[7]=t1.w;
    } else {
        #pragma unroll
        for (int j = 0; j < 8; j++) {
            int n = n0 + bCol + j;
            rbv[j] = (n < ldb) ? B[(size_t)bRow * ldb + n] : 0.f;
        }
    }

    float acc[4][4][4] = {};

    for (int k0 = 0; k0 < K; k0 += 16) {
        st_pair8(&As[aRow][aCol], ra0, ra1);
        #pragma unroll
        for (int j = 0; j < 8; j++) Bs[bRow][bCol + j] = f2tff(rbv[j]);
        __syncthreads();

        if (k0 + 16 < K) {
            ra0 = *(const float4*)(Ap + k0 + 16);
            ra1 = *(const float4*)(Ap + k0 + 20);
            if (fastB) {
                const float* bp = B + (size_t)(k0 + 16 + bRow) * ldb + n0 + bCol;
                float4 t0 = *(const float4*)bp, t1 = *(const float4*)(bp + 4);
                rbv[0]=t0.x; rbv[1]=t0.y; rbv[2]=t0.z; rbv[3]=t0.w;
                rbv[4]=t1.x; rbv[5]=t1.y; rbv[6]=t1.z; rbv[7]=t1.w;
            } else {
                #pragma unroll
                for (int j = 0; j < 8; j++) {
                    int n = n0 + bCol + j;
                    rbv[j] = (n < ldb) ? B[(size_t)(k0 + 16 + bRow) * ldb + n] : 0.f;
                }
            }
        }

        #pragma unroll
        for (int kk = 0; kk < 16; kk += 8) {
            unsigned af[4][4], bf[4][2];
            #pragma unroll
            for (int mt = 0; mt < 4; mt++) {
                int r = wm + mt * 16 + g;
                float2 pa = *(const float2*)&As[r][kk + 2 * tig];
                float2 pb = *(const float2*)&As[r + 8][kk + 2 * tig];
                af[mt][0] = __float_as_uint(pa.x);
                af[mt][1] = __float_as_uint(pb.x);
                af[mt][2] = __float_as_uint(pa.y);
                af[mt][3] = __float_as_uint(pb.y);
            }
            #pragma unroll
            for (int nt = 0; nt < 4; nt++) {
                int c = wn + nt * 8 + g;
                bf[nt][0] = __float_as_uint(Bs[kk + tig][c]);
                bf[nt][1] = __float_as_uint(Bs[kk + tig + 4][c]);
            }
            #pragma unroll
            for (int mt = 0; mt < 4; mt++)
                #pragma unroll
                for (int nt = 0; nt < 4; nt++)
                    mma_tf32(acc[mt][nt], af[mt], bf[nt]);
        }
        __syncthreads();
    }

    #pragma unroll
    for (int mt = 0; mt < 4; mt++) {
        #pragma unroll
        for (int nt = 0; nt < 4; nt++) {
            int row = m0 + wm + mt * 16 + g;
            int col = n0 + wn + nt * 8 + 2 * tig;
            float c0 = acc[mt][nt][0], c1 = acc[mt][nt][1];
            float c2 = acc[mt][nt][2], c3 = acc[mt][nt][3];
            if (fastC) {
                float b0 = bias ? bias[col] : 0.f;
                float b1 = bias ? bias[col + 1] : 0.f;
                c0 += b0; c1 += b1; c2 += b0; c3 += b1;
                if (act == 1) { c0 = gelu_f(c0); c1 = gelu_f(c1); c2 = gelu_f(c2); c3 = gelu_f(c3); }
                *(float2*)&C[(size_t)row * N + col]       = make_float2(c0, c1);
                *(float2*)&C[(size_t)(row + 8) * N + col] = make_float2(c2, c3);
            } else {
                if (col < N) {
                    float b0 = bias ? bias[col] : 0.f;
                    float u0 = c0 + b0, u2 = c2 + b0;
                    if (act == 1) { u0 = gelu_f(u0); u2 = gelu_f(u2); }
                    C[(size_t)row * N + col] = u0;
                    C[(size_t)(row + 8) * N + col] = u2;
                }
                if (col + 1 < N) {
                    float b1 = bias ? bias[col + 1] : 0.f;
                    float u1 = c1 + b1, u3 = c3 + b1;
                    if (act == 1) { u1 = gelu_f(u1); u3 = gelu_f(u3); }
                    C[(size_t)row * N + col + 1] = u1;
                    C[(size_t)(row + 8) * N + col + 1] = u3;
                }
            }
        }
    }
}

__global__ void __launch_bounds__(256, 2)
k_gmma(const float* __restrict__ A, const float* __restrict__ B,
       const float* __restrict__ bias, float* __restrict__ C,
       int N, int ldb, int K, int act)
{
    __shared__ float As[128][24];
    __shared__ float Bs[16][136];
    gmma_core(A, B, bias, C, N, ldb, K, act, blockIdx.y * 128, blockIdx.x * 128, As, Bs);
}

// m-fastest grid — vocab GEMM L2 reuse of B across waves
__global__ void __launch_bounds__(256, 2)
k_gmma_m(const float* __restrict__ A, const float* __restrict__ B,
         const float* __restrict__ bias, float* __restrict__ C,
         int N, int ldb, int K, int act)
{
    __shared__ float As[128][24];
    __shared__ float Bs[16][136];
    gmma_core(A, B, bias, C, N, ldb, K, act, blockIdx.x * 128, blockIdx.y * 128, As, Bs);
}

// fused QKV
__global__ void __launch_bounds__(256, 2)
k_qkv(const float* __restrict__ X, const float* __restrict__ Wq,
      const float* __restrict__ Wk, const float* __restrict__ Wv,
      float* __restrict__ QKV)
{
    __shared__ float As[128][24];
    __shared__ float Bs[16][136];
    int z = blockIdx.z;
    const float* W = (z == 0) ? Wq : (z == 1) ? Wk : Wv;
    float* O = QKV + (size_t)z * NT * DD;
    gmma_core(X, W, nullptr, O, DD, DD, DD, 0, blockIdx.y * 128, blockIdx.x * 128, As, Bs);
}

// =====================================================================
// Flash attention v3: CTA = (bh, 128 q rows); key tile 64; 8 warps x 16 rows.
// Pair-interleaved Q/K/P (stride 72, conflict-free LDS.64); V plain pad 72.
// smem 110.8 KB -> 2 CTAs/SM; all 192 CTAs in one wave.
// =====================================================================
#define FA_SMEM ((128*72 + 64*72 + 64*72 + 128*72 + 64) * 4)

__global__ void __launch_bounds__(256, 2)
k_fattn(const float* __restrict__ Q, const float* __restrict__ K,
        const float* __restrict__ V, const int* __restrict__ mask,
        float* __restrict__ ctx)
{
    extern __shared__ float sm[];
    float* Qs  = sm;                        // [128][72] pair-interleaved dk
    float* Ks  = Qs + 128*72;               // [64][72]  pair-interleaved dk
    float* Vs  = Ks + 64*72;                // [64][72]  plain [k][d]
    float* Ps  = Vs + 64*72;                // [128][72] pair-interleaved keys
    float* msk = Ps + 128*72;               // [64]

    int bh = blockIdx.y;
    int b = bh / NH, h = bh - b * NH;
    int i0 = blockIdx.x * 128;

    const float* qb = Q + (size_t)b * SQ * DD + h * DK;
    const float* kb = K + (size_t)b * SQ * DD + h * DK;
    const float* vb = V + (size_t)b * SQ * DD + h * DK;
    float* cb = ctx + (size_t)b * SQ * DD + h * DK;
    const int* mrow = mask + (size_t)b * SQ;

    int tid = threadIdx.x;
    int lane = tid & 31, w = tid >> 5;
    int g = lane >> 2, tig = lane & 3;
    int wr = w * 16;

    // load Q tile, pair-interleaved over dk
    {
        int r = tid >> 1;
        int c0 = (tid & 1) * 32;
        const float* qp = qb + (size_t)(i0 + r) * DD + c0;
        float* qs = Qs + r * 72 + c0;
        #pragma unroll
        for (int i = 0; i < 4; i++) {
            float4 lo = *(const float4*)(qp + 8 * i);
            float4 hi = *(const float4*)(qp + 8 * i + 4);
            st_pair8(qs + 8 * i, lo, hi);
        }
    }

    // interleaved position of key 2*tig within its 8-block (pair order)
    int p0 = (tig < 2) ? 4 * tig : 4 * (tig - 2) + 1;   // key j*8+2tig; +2 for next key

    float oacc[8][4] = {};
    float mr0 = -1e30f, mr1 = -1e30f, l0 = 0.f, l1 = 0.f;

    for (int kt = 0; kt < SQ; kt += 64) {
        __syncthreads();   // previous tile reads done
        {
            int r = tid >> 2;                // 0..63
            int c0 = (tid & 3) * 16;         // 0,16,32,48
            const float* kp = kb + (size_t)(kt + r) * DD + c0;
            const float* vp = vb + (size_t)(kt + r) * DD + c0;
            float* ks = Ks + r * 72 + c0;
            float* vs = Vs + r * 72 + c0;
            #pragma unroll
            for (int i = 0; i < 2; i++) {
                float4 lo = *(const float4*)(kp + 8 * i);
                float4 hi = *(const float4*)(kp + 8 * i + 4);
                st_pair8(ks + 8 * i, lo, hi);
                float4 v0 = *(const float4*)(vp + 8 * i);
                float4 v1 = *(const float4*)(vp + 8 * i + 4);
                *(float4*)(vs + 8*i)     = make_float4(f2tff(v0.x), f2tff(v0.y), f2tff(v0.z), f2tff(v0.w));
                *(float4*)(vs + 8*i + 4) = make_float4(f2tff(v1.x), f2tff(v1.y), f2tff(v1.z), f2tff(v1.w));
            }
            if (tid < 64) msk[tid] = (mrow[kt + tid] == 0) ? -1e9f : 0.f;
        }
        __syncthreads();

        // S = Q @ K^T : 16 rows x 64 keys per warp
        float sacc[8][4] = {};
        #pragma unroll
        for (int kk = 0; kk < DK; kk += 8) {
            unsigned af[4];
            {
                float2 pa = *(const float2*)(Qs + (wr + g) * 72 + kk + 2 * tig);
                float2 pb = *(const float2*)(Qs + (wr + g + 8) * 72 + kk + 2 * tig);
                af[0] = __float_as_uint(pa.x); af[1] = __float_as_uint(pb.x);
                af[2] = __float_as_uint(pa.y); af[3] = __float_as_uint(pb.y);
            }
            #pragma unroll
            for (int j = 0; j < 8; j++) {
                unsigned bf[2];
                float2 pk = *(const float2*)(Ks + (j * 8 + g) * 72 + kk + 2 * tig);
                bf[0] = __float_as_uint(pk.x);
                bf[1] = __float_as_uint(pk.y);
                mma_tf32(sacc[j], af, bf);
            }
        }

        // scale + mask + tile row max
        float tm0 = -1e30f, tm1 = -1e30f;
        #pragma unroll
        for (int j = 0; j < 8; j++) {
            int c = j * 8 + 2 * tig;
            float a0 = msk[c], a1 = msk[c + 1];
            sacc[j][0] = sacc[j][0] * 0.125f + a0;
            sacc[j][1] = sacc[j][1] * 0.125f + a1;
            sacc[j][2] = sacc[j][2] * 0.125f + a0;
            sacc[j][3] = sacc[j][3] * 0.125f + a1;
            tm0 = fmaxf(tm0, fmaxf(sacc[j][0], sacc[j][1]));
            tm1 = fmaxf(tm1, fmaxf(sacc[j][2], sacc[j][3]));
        }
        tm0 = fmaxf(tm0, __shfl_xor_sync(0xffffffffu, tm0, 1));
        tm0 = fmaxf(tm0, __shfl_xor_sync(0xffffffffu, tm0, 2));
        tm1 = fmaxf(tm1, __shfl_xor_sync(0xffffffffu, tm1, 1));
        tm1 = fmaxf(tm1, __shfl_xor_sync(0xffffffffu, tm1, 2));

        float mn0 = fmaxf(mr0, tm0), mn1 = fmaxf(mr1, tm1);
        float al0 = __expf(mr0 - mn0), al1 = __expf(mr1 - mn1);

        __syncwarp();   // prior P@V reads done before overwriting Ps
        float ts0 = 0.f, ts1 = 0.f;
        #pragma unroll
        for (int j = 0; j < 8; j++) {
            float p0v = __expf(sacc[j][0] - mn0);
            float p1v = __expf(sacc[j][1] - mn0);
            float p2v = __expf(sacc[j][2] - mn1);
            float p3v = __expf(sacc[j][3] - mn1);
            ts0 += p0v + p1v;
            ts1 += p2v + p3v;
            float* pr0 = Ps + (wr + g) * 72 + j * 8;
            float* pr1 = Ps + (wr + g + 8) * 72 + j * 8;
            pr0[p0]     = f2tff(p0v);
            pr0[p0 + 2] = f2tff(p1v);
            pr1[p0]     = f2tff(p2v);
            pr1[p0 + 2] = f2tff(p3v);
        }
        ts0 += __shfl_xor_sync(0xffffffffu, ts0, 1);
        ts0 += __shfl_xor_sync(0xffffffffu, ts0, 2);
        ts1 += __shfl_xor_sync(0xffffffffu, ts1, 1);
        ts1 += __shfl_xor_sync(0xffffffffu, ts1, 2);
        l0 = l0 * al0 + ts0;
        l1 = l1 * al1 + ts1;
        mr0 = mn0; mr1 = mn1;

        #pragma unroll
        for (int j = 0; j < 8; j++) {
            oacc[j][0] *= al0; oacc[j][1] *= al0;
            oacc[j][2] *= al1; oacc[j][3] *= al1;
        }
        __syncwarp();   // Ps stores visible within warp

        // O += P @ V (64 keys, 64 d cols)
        #pragma unroll
        for (int kk = 0; kk < 64; kk += 8) {
            unsigned af[4];
            {
                float2 pa = *(const float2*)(Ps + (wr + g) * 72 + kk + 2 * tig);
                float2 pb = *(const float2*)(Ps + (wr + g + 8) * 72 + kk + 2 * tig);
                af[0] = __float_as_uint(pa.x); af[1] = __float_as_uint(pb.x);
                af[2] = __float_as_uint(pa.y); af[3] = __float_as_uint(pb.y);
            }
            #pragma unroll
            for (int j = 0; j < 8; j++) {
                unsigned bf[2];
                const float* vp = Vs + (kk + tig) * 72 + j * 8 + g;
                bf[0] = __float_as_uint(vp[0]);
                bf[1] = __float_as_uint(vp[4 * 72]);
                mma_tf32(oacc[j], af, bf);
            }
        }
    }

    float il0 = 1.f / l0, il1 = 1.f / l1;
    int r0 = i0 + wr + g;
    #pragma unroll
    for (int j = 0; j < 8; j++) {
        int c = j * 8 + 2 * tig;
        *(float2*)&cb[(size_t)r0 * DD + c] =
            make_float2(oacc[j][0] * il0, oacc[j][1] * il0);
        *(float2*)&cb[(size_t)(r0 + 8) * DD + c] =
            make_float2(oacc[j][2] * il1, oacc[j][3] * il1);
    }
}

// ---------------- out = LayerNorm(x (+ res)) * g + b ----------------
__global__ void k_addln(const float* __restrict__ X, const float* __restrict__ R,
                        const float* __restrict__ g, const float* __restrict__ bb,
                        float* __restrict__ O)
{
    int r = blockIdx.x;
    const float* xr = X + (size_t)r * DD;
    const float* rr = R ? (R + (size_t)r * DD) : nullptr;
    float* orow = O + (size_t)r * DD;

    int tid = threadIdx.x;
    __shared__ float rbuf[8];

    float v[3];
    float s = 0.f;
    #pragma unroll
    for (int j = 0; j < 3; j++) {
        int c = tid * 3 + j;
        float x = xr[c];
        if (rr) x += rr[c];
        v[j] = x;
        s += x;
    }
    #pragma unroll
    for (int o = 16; o; o >>= 1) s += __shfl_xor_sync(0xffffffffu, s, o);
    __syncthreads();
    if ((tid & 31) == 0) rbuf[tid >> 5] = s;
    __syncthreads();
    s = rbuf[0];
    #pragma unroll
    for (int w = 1; w < 8; w++) s += rbuf[w];
    float mean = s * (1.f / DD);

    float s2 = 0.f;
    #pragma unroll
    for (int j = 0; j < 3; j++) { float d = v[j] - mean; s2 += d * d; }
    #pragma unroll
    for (int o = 16; o; o >>= 1) s2 += __shfl_xor_sync(0xffffffffu, s2, o);
    __syncthreads();
    if ((tid & 31) == 0) rbuf[tid >> 5] = s2;
    __syncthreads();
    s2 = rbuf[0];
    #pragma unroll
    for (int w = 1; w < 8; w++) s2 += rbuf[w];
    float rstd = rsqrtf(s2 * (1.f / DD) + 1e-5f);

    #pragma unroll
    for (int j = 0; j < 3; j++) {
        int c = tid * 3 + j;
        orow[c] = (v[j] - mean) * rstd * g[c] + bb[c];
    }
}

// ---------------- driver ----------------
extern "C" void kernel_launch(void* const* d_in, const int* in_sizes, int n_in,
                              void* d_out, int out_size)
{
    const int*   ids  = (const int*)  d_in[0];
    const int*   mask = (const int*)  d_in[1];
    const float* emb  = (const float*)d_in[2];
    const float* pe   = (const float*)d_in[3];
    const float* Wq   = (const float*)d_in[4];
    const float* Wk   = (const float*)d_in[5];
    const float* Wv   = (const float*)d_in[6];
    const float* Wo   = (const float*)d_in[7];
    const float* ln1g = (const float*)d_in[8];
    const float* ln1b = (const float*)d_in[9];
    const float* ln2g = (const float*)d_in[10];
    const float* ln2b = (const float*)d_in[11];
    const float* W1   = (const float*)d_in[12];
    const float* b1   = (const float*)d_in[13];
    const float* W2   = (const float*)d_in[14];
    const float* b2   = (const float*)d_in[15];
    const float* lnfg = (const float*)d_in[16];
    const float* lnfb = (const float*)d_in[17];
    const float* Wout = (const float*)d_in[18];
    const float* bout = (const float*)d_in[19];
    float* out = (float*)d_out;

    float *x, *qkv, *ctx, *tmp, *h, *wpad;
    cudaGetSymbolAddress((void**)&x,    g_x);
    cudaGetSymbolAddress((void**)&qkv,  g_qkv);
    cudaGetSymbolAddress((void**)&ctx,  g_ctx);
    cudaGetSymbolAddress((void**)&tmp,  g_tmp);
    cudaGetSymbolAddress((void**)&h,    g_h);
    cudaGetSymbolAddress((void**)&wpad, g_wpad);

    float* q = qkv;
    float* k = qkv + (size_t)NT * DD;
    float* v = qkv + (size_t)2 * NT * DD;

    cudaFuncSetAttribute(k_fattn, cudaFuncAttributeMaxDynamicSharedMemorySize, FA_SMEM);

    k_embed<<<(NT * DD + 255) / 256, 256>>>(ids, emb, pe, x);
    k_padw<<<(int)(((long long)DD * NVP + 255) / 256), 256>>>(Wout, wpad);

    dim3 gQKV(DD / 128, NT / 128, 3);
    dim3 gD(DD / 128, NT / 128);
    dim3 gF(FF / 128, NT / 128);
    dim3 gV(NT / 128, NVP / 128);
    dim3 gA(SQ / 128, BB * NH);

    for (int l = 0; l < NL; l++) {
        const float* wq = Wq + (size_t)l * DD * DD;
        const float* wk = Wk + (size_t)l * DD * DD;
        const float* wv = Wv + (size_t)l * DD * DD;
        const float* wo = Wo + (size_t)l * DD * DD;

        k_qkv<<<gQKV, 256>>>(x, wq, wk, wv, qkv);

        k_fattn<<<gA, 256, FA_SMEM>>>(q, k, v, mask, ctx);

        k_gmma<<<gD, 256>>>(ctx, wo, nullptr, tmp, DD, DD, DD, 0);
        k_addln<<<NT, 256>>>(x, tmp, ln1g + (size_t)l * DD, ln1b + (size_t)l * DD, x);

        k_gmma<<<gF, 256>>>(x, W1 + (size_t)l * DD * FF, b1 + (size_t)l * FF, h, FF, FF, DD, 1);
        k_gmma<<<gD, 256>>>(h, W2 + (size_t)l * FF * DD, b2 + (size_t)l * DD, tmp, DD, DD, FF, 0);
        k_addln<<<NT, 256>>>(x, tmp, ln2g + (size_t)l * DD, ln2b + (size_t)l * DD, x);
    }

    k_addln<<<NT, 256>>>(x, nullptr, lnfg, lnfb, x);

    k_gmma_m<<<gV, 256>>>(x, wpad, bout, out, NV, NVP, DD, 0);
}